// round 14
// baseline (speedup 1.0000x reference)
#include <cuda_runtime.h>
#include <cuda_fp16.h>
#include <math.h>
#include <stdint.h>

#define B 2
#define S 2048
#define D 2048
#define H 16
#define HKV 4
#define HD 128
#define M_ROWS (B*S)     // 4096
#define QN (H*HD)        // 2048
#define KN (HKV*HD)      // 512

// Scratch (allocation-free: device globals), fp16 operands everywhere
__device__ __half g_xh[(size_t)M_ROWS * D];
__device__ __half g_wqT[(size_t)QN * D];    // [N][K]
__device__ __half g_wkT[(size_t)KN * D];
__device__ __half g_wvT[(size_t)KN * D];
__device__ __half g_woT[(size_t)D * QN];
__device__ __half g_qh[(size_t)M_ROWS * QN];
__device__ __half g_kh[(size_t)M_ROWS * KN];
__device__ __half g_vT[(size_t)B * HKV * HD * S];  // [b][hk][d][s]
__device__ __half g_attnh[(size_t)M_ROWS * QN];

#define MMA_F16(c, a, b)                                                      \
  asm("mma.sync.aligned.m16n8k16.row.col.f32.f16.f16.f32 "                    \
      "{%0,%1,%2,%3},{%4,%5,%6,%7},{%8,%9},{%0,%1,%2,%3};"                    \
      : "+f"(c[0]), "+f"(c[1]), "+f"(c[2]), "+f"(c[3])                        \
      : "r"(a[0]), "r"(a[1]), "r"(a[2]), "r"(a[3]), "r"(b[0]), "r"(b[1]))

#define LDSM4(r0, r1, r2, r3, addr)                                           \
  asm volatile("ldmatrix.sync.aligned.m8n8.x4.shared.b16 {%0,%1,%2,%3}, [%4];"\
               : "=r"(r0), "=r"(r1), "=r"(r2), "=r"(r3) : "r"(addr))

#define CP16(dst, src)                                                        \
  asm volatile("cp.async.cg.shared.global [%0], [%1], 16;" ::"r"(dst), "l"(src))
#define CP_COMMIT() asm volatile("cp.async.commit_group;")
#define CP_WAIT1()  asm volatile("cp.async.wait_group 1;")
#define CP_WAIT2()  asm volatile("cp.async.wait_group 2;")
#define CP_WAIT3()  asm volatile("cp.async.wait_group 3;")

// ---------------------------------------------------------------------------
// fp32 -> fp16 convert (x), batched tiled transpose+convert (all 4 weights)
// ---------------------------------------------------------------------------
__global__ void conv_half(const float* __restrict__ src,
                          __half* __restrict__ dst, int n4) {
  int i = blockIdx.x * blockDim.x + threadIdx.x;
  if (i < n4) {
    float4 v = *(const float4*)(src + 4 * (size_t)i);
    *(__half2*)(dst + 4 * (size_t)i) = __floats2half2_rn(v.x, v.y);
    *(__half2*)(dst + 4 * (size_t)i + 2) = __floats2half2_rn(v.z, v.w);
  }
}

__global__ void transpose_all(const float* __restrict__ Wq,
                              const float* __restrict__ Wk,
                              const float* __restrict__ Wv,
                              const float* __restrict__ Wo,
                              __half* __restrict__ wqT, __half* __restrict__ wkT,
                              __half* __restrict__ wvT, __half* __restrict__ woT) {
  __shared__ float t[32][33];
  const float* src;
  __half* dst;
  int R, C;
  switch (blockIdx.z) {
    case 0: src = Wq; dst = wqT; R = D;  C = QN; break;
    case 1: src = Wk; dst = wkT; R = D;  C = KN; break;
    case 2: src = Wv; dst = wvT; R = D;  C = KN; break;
    default: src = Wo; dst = woT; R = QN; C = D;  break;
  }
  int c0 = blockIdx.x * 32, r0 = blockIdx.y * 32;
  if (c0 >= C || r0 >= R) return;
  int x = threadIdx.x, y = threadIdx.y;
#pragma unroll
  for (int i = 0; i < 32; i += 8)
    t[y + i][x] = src[(size_t)(r0 + y + i) * C + c0 + x];
  __syncthreads();
#pragma unroll
  for (int i = 0; i < 32; i += 8)
    dst[(size_t)(c0 + y + i) * R + r0 + x] = __float2half_rn(t[x][y + i]);
}

// ---------------------------------------------------------------------------
// fp16 MMA GEMM: 128x128x32 block tile, 128 threads (4 warps, warp 64x64),
// 3-buffer single-barrier cp.async pipeline, ldmatrix fragments, 2 CTAs/SM.
// Epilogues: 0 half, 1 V^T half, 2 fp32, 3 half + fused RoPE (Q/K proj).
// ---------------------------------------------------------------------------
#define AS_STRIDE 40
#define BS_STRIDE 40
#define AS_SZ (128 * AS_STRIDE)
#define BS_SZ (128 * BS_STRIDE)
#define GEMM_SMEM_BYTES (3 * (AS_SZ + BS_SZ) * 2)

__device__ __forceinline__ void gemm_issue_slab(
    int tid, const __half* __restrict__ A, const __half* __restrict__ BT,
    int K, int row0, int col0, int k0, __half* as, __half* bs) {
#pragma unroll
  for (int l = 0; l < 4; l++) {
    int idx = tid + l * 128;
    int ar = idx >> 2, ac = (idx & 3) << 3;
    const __half* asrc = A + (size_t)(row0 + ar) * K + k0 + ac;
    uint32_t adst = (uint32_t)__cvta_generic_to_shared(as + ar * AS_STRIDE + ac);
    CP16(adst, asrc);
  }
#pragma unroll
  for (int l = 0; l < 4; l++) {
    int idx = tid + l * 128;
    int br = idx >> 2, bc = (idx & 3) << 3;
    const __half* bsrc = BT + (size_t)(col0 + br) * K + k0 + bc;
    uint32_t bdst = (uint32_t)__cvta_generic_to_shared(bs + br * BS_STRIDE + bc);
    CP16(bdst, bsrc);
  }
}

template <int MODE>
__device__ __forceinline__ void gemm_body(
    const __half* __restrict__ A, const __half* __restrict__ BT,
    void* __restrict__ Cv, int N, int K, int row0, int col0, __half* smp,
    int vb_base) {
  __half* As = smp;                 // 3 x [128][40]
  __half* Bs = smp + 3 * AS_SZ;     // 3 x [128][40]

  const int tid = threadIdx.x;
  const int lane = tid & 31;
  const int w = tid >> 5;
  const int g = lane >> 2;
  const int t4 = lane & 3;
  const int warp_m = w & 1, warp_n = w >> 1;
  const int m0w = warp_m * 64, n0w = warp_n * 64;

  const int a_lrow = (lane & 7) + ((lane >> 3) & 1) * 8;
  const int a_koff = (lane >> 4) * 8;
  const int b_lrow = (lane & 7) + (lane >> 4) * 8;
  const int b_koff = ((lane >> 3) & 1) * 8;

  float acc[4][8][4];
#pragma unroll
  for (int mi = 0; mi < 4; mi++)
#pragma unroll
    for (int ni = 0; ni < 8; ni++)
#pragma unroll
      for (int e = 0; e < 4; e++) acc[mi][ni][e] = 0.f;

  gemm_issue_slab(tid, A, BT, K, row0, col0, 0, As, Bs);
  CP_COMMIT();
  gemm_issue_slab(tid, A, BT, K, row0, col0, 32, As + AS_SZ, Bs + BS_SZ);
  CP_COMMIT();

  const uint32_t asu0 = (uint32_t)__cvta_generic_to_shared(As);
  const uint32_t bsu0 = (uint32_t)__cvta_generic_to_shared(Bs);

  const int nslab = K >> 5;
  for (int it = 0; it < nslab; it++) {
    CP_WAIT1();
    __syncthreads();
    int kn = it + 2;
    if (kn < nslab)
      gemm_issue_slab(tid, A, BT, K, row0, col0, kn << 5,
                      As + (kn % 3) * AS_SZ, Bs + (kn % 3) * BS_SZ);
    CP_COMMIT();

    const uint32_t asu = asu0 + (it % 3) * AS_SZ * 2;
    const uint32_t bsu = bsu0 + (it % 3) * BS_SZ * 2;
#pragma unroll
    for (int ks = 0; ks < 2; ks++) {
      const int kk = ks * 16;
      uint32_t a[4][4];
#pragma unroll
      for (int mi = 0; mi < 4; mi++) {
        uint32_t ad = asu +
            ((m0w + mi * 16 + a_lrow) * AS_STRIDE + kk + a_koff) * 2;
        LDSM4(a[mi][0], a[mi][1], a[mi][2], a[mi][3], ad);
      }
      uint32_t b[8][2];
#pragma unroll
      for (int nip = 0; nip < 4; nip++) {
        uint32_t bd = bsu +
            ((n0w + nip * 16 + b_lrow) * BS_STRIDE + kk + b_koff) * 2;
        LDSM4(b[2 * nip][0], b[2 * nip][1], b[2 * nip + 1][0],
              b[2 * nip + 1][1], bd);
      }
#pragma unroll
      for (int mi = 0; mi < 4; mi++)
#pragma unroll
        for (int ni = 0; ni < 8; ni++) MMA_F16(acc[mi][ni], a[mi], b[ni]);
    }
  }

#pragma unroll
  for (int mi = 0; mi < 4; mi++) {
    int r0 = row0 + m0w + mi * 16 + g;
#pragma unroll
    for (int ni = 0; ni < 8; ni++) {
      int col = col0 + n0w + ni * 8 + 2 * t4;
      if (MODE == 0) {
        __half* C = (__half*)Cv;
        *(__half2*)(C + (size_t)r0 * N + col) =
            __floats2half2_rn(acc[mi][ni][0], acc[mi][ni][1]);
        *(__half2*)(C + (size_t)(r0 + 8) * N + col) =
            __floats2half2_rn(acc[mi][ni][2], acc[mi][ni][3]);
      } else if (MODE == 1) {
        __half* C = (__half*)Cv;
        int s0 = r0 & (S - 1);
        int b0 = r0 >> 11;
        int d = col & (HD - 1);
        __half* base = C + ((size_t)(b0 * HKV) + vb_base) * HD * S;
        base[(size_t)d * S + s0] = __float2half_rn(acc[mi][ni][0]);
        base[(size_t)(d + 1) * S + s0] = __float2half_rn(acc[mi][ni][1]);
        base[(size_t)d * S + s0 + 8] = __float2half_rn(acc[mi][ni][2]);
        base[(size_t)(d + 1) * S + s0 + 8] = __float2half_rn(acc[mi][ni][3]);
      } else if (MODE == 2) {
        float* C = (float*)Cv;
        *(float2*)(C + (size_t)r0 * N + col) =
            make_float2(acc[mi][ni][0], acc[mi][ni][1]);
        *(float2*)(C + (size_t)(r0 + 8) * N + col) =
            make_float2(acc[mi][ni][2], acc[mi][ni][3]);
      } else {  // MODE 3: fused RoPE. Thread holds cols (2j, 2j+1) of one head.
        __half* C = (__half*)Cv;
        const int s0 = r0 & (S - 1);
        const int jj = (col & 127) >> 1;
        const int cb = col - (col & 127);
        const float theta = exp2f(-(float)jj * 0.20762050593045983f);
        float sn0, cs0, sn1, cs1;
        sincosf((float)s0 * theta, &sn0, &cs0);
        sincosf((float)(s0 + 8) * theta, &sn1, &cs1);
        __half* p0 = C + (size_t)r0 * N + cb + jj;
        __half* p1 = C + (size_t)(r0 + 8) * N + cb + jj;
        p0[0]  = __float2half_rn(acc[mi][ni][0] * cs0 - acc[mi][ni][1] * sn0);
        p0[64] = __float2half_rn(acc[mi][ni][0] * sn0 + acc[mi][ni][1] * cs0);
        p1[0]  = __float2half_rn(acc[mi][ni][2] * cs1 - acc[mi][ni][3] * sn1);
        p1[64] = __float2half_rn(acc[mi][ni][2] * sn1 + acc[mi][ni][3] * cs1);
      }
    }
  }
}

__global__ void __launch_bounds__(128, 2)
qkv_gemm(const __half* __restrict__ xh, const __half* __restrict__ wqT,
         const __half* __restrict__ wkT, const __half* __restrict__ wvT,
         __half* __restrict__ q, __half* __restrict__ k,
         __half* __restrict__ vT) {
  extern __shared__ __half smp[];
  const int bx = blockIdx.x;
  const int row0 = blockIdx.y * 128;
  if (bx < 16) {
    gemm_body<3>(xh, wqT, q, QN, D, row0, bx * 128, smp, 0);        // Q + RoPE
  } else if (bx < 20) {
    gemm_body<3>(xh, wkT, k, KN, D, row0, (bx - 16) * 128, smp, 0); // K + RoPE
  } else {
    int col0 = (bx - 20) * 128;
    gemm_body<1>(xh, wvT, vT, KN, D, row0, col0, smp, col0 >> 7);
  }
}

__global__ void __launch_bounds__(128, 2)
o_gemm(const __half* __restrict__ attnh, const __half* __restrict__ woT,
       float* __restrict__ out) {
  extern __shared__ __half smp[];
  gemm_body<2>(attnh, woT, out, D, QN, blockIdx.y * 128, blockIdx.x * 128, smp, 0);
}

// ---------------------------------------------------------------------------
// Flash attention (R11 verbatim): 256 threads, 8 warps x 16 q-rows, k-tile 128,
// double-buffered K/V (4 cp.async groups), register softmax.
// ---------------------------------------------------------------------------
#define QS_STRIDE 136
#define KS_STRIDE 136
#define VT_STRIDE 136
#define KS_SZ (128 * KS_STRIDE)
#define VS_SZ (128 * VT_STRIDE)
#define ATTN_SMEM_BYTES ((128 * QS_STRIDE + 2 * KS_SZ + 2 * VS_SZ) * 2)

__device__ __forceinline__ void attn_issue_k(int tid, const __half* src,
                                             __half* dst) {
#pragma unroll
  for (int i = 0; i < 8; i++) {
    int idx = tid + i * 256;
    int n = idx >> 4, c8 = (idx & 15) << 3;
    uint32_t d = (uint32_t)__cvta_generic_to_shared(dst + n * KS_STRIDE + c8);
    CP16(d, src + (size_t)n * KN + c8);
  }
}
__device__ __forceinline__ void attn_issue_v(int tid, const __half* src,
                                             __half* dst) {
#pragma unroll
  for (int i = 0; i < 8; i++) {
    int idx = tid + i * 256;
    int dd = idx >> 4, c8 = (idx & 15) << 3;
    uint32_t d = (uint32_t)__cvta_generic_to_shared(dst + dd * VT_STRIDE + c8);
    CP16(d, src + (size_t)dd * S + c8);
  }
}

__global__ void __launch_bounds__(256, 1)
attn_kernel(const __half* __restrict__ Q, const __half* __restrict__ K,
            const __half* __restrict__ VT, __half* __restrict__ O) {
  extern __shared__ __half smh[];
  __half* Qs = smh;
  __half* Ks = Qs + 128 * QS_STRIDE;
  __half* Vs = Ks + 2 * KS_SZ;

  const int tid = threadIdx.x;
  const int lane = tid & 31;
  const int w = tid >> 5;
  const int g = lane >> 2;
  const int t4 = lane & 3;
  const int m0 = w * 16;

  const int a_lrow = (lane & 7) + ((lane >> 3) & 1) * 8;
  const int a_koff = (lane >> 4) * 8;
  const int b_lrow = (lane & 7) + (lane >> 4) * 8;
  const int b_koff = ((lane >> 3) & 1) * 8;

  const uint32_t qsu = (uint32_t)__cvta_generic_to_shared(Qs);
  const uint32_t ksu0 = (uint32_t)__cvta_generic_to_shared(Ks);
  const uint32_t vsu0 = (uint32_t)__cvta_generic_to_shared(Vs);

  const int qi = (int)gridDim.x - 1 - (int)blockIdx.x;
  const int bh = blockIdx.y;
  const int b = bh >> 4;
  const int h = bh & 15;
  const int hk = h >> 2;
  const int q0 = qi * 128;

  const __half* qb = Q + (size_t)b * S * QN + h * HD;
  const __half* kb = K + (size_t)b * S * KN + hk * HD;
  const __half* vtb = VT + ((size_t)(b * HKV + hk)) * HD * S;

  const int T = qi + 1;

#pragma unroll
  for (int i = 0; i < 8; i++) {
    int idx = tid + i * 256;
    int r = idx >> 4, c8 = (idx & 15) << 3;
    uint32_t d = (uint32_t)__cvta_generic_to_shared(Qs + r * QS_STRIDE + c8);
    CP16(d, qb + (size_t)(q0 + r) * QN + c8);
  }
  attn_issue_k(tid, kb, Ks);
  CP_COMMIT();
  attn_issue_v(tid, vtb, Vs);
  CP_COMMIT();
  attn_issue_k(tid, kb + (size_t)128 * KN, Ks + KS_SZ);
  CP_COMMIT();
  attn_issue_v(tid, vtb + 128, Vs + VS_SZ);
  CP_COMMIT();

  float oacc[16][4];
#pragma unroll
  for (int ni = 0; ni < 16; ni++)
#pragma unroll
    for (int e = 0; e < 4; e++) oacc[ni][e] = 0.f;

  float m0r = -INFINITY, m1r = -INFINITY;
  float l0r = 0.f, l1r = 0.f;

  const float qk_scale = 0.08838834764831845f;

  for (int t = 0; t < T; t++) {
    const int k0 = t << 7;
    const uint32_t ksu = ksu0 + (t & 1) * KS_SZ * 2;
    const uint32_t vsu = vsu0 + (t & 1) * VS_SZ * 2;

    CP_WAIT3();
    __syncthreads();

    float sacc[16][4];
#pragma unroll
    for (int ni = 0; ni < 16; ni++)
#pragma unroll
      for (int e = 0; e < 4; e++) sacc[ni][e] = 0.f;

#pragma unroll
    for (int ks = 0; ks < 8; ks++) {
      const int kk = ks * 16;
      uint32_t a[4];
      uint32_t ad = qsu + ((m0 + a_lrow) * QS_STRIDE + kk + a_koff) * 2;
      LDSM4(a[0], a[1], a[2], a[3], ad);
      uint32_t bfr[16][2];
#pragma unroll
      for (int nip = 0; nip < 8; nip++) {
        uint32_t bd = ksu + ((nip * 16 + b_lrow) * KS_STRIDE + kk + b_koff) * 2;
        LDSM4(bfr[2 * nip][0], bfr[2 * nip][1], bfr[2 * nip + 1][0],
              bfr[2 * nip + 1][1], bd);
      }
#pragma unroll
      for (int ni = 0; ni < 16; ni++) MMA_F16(sacc[ni], a, bfr[ni]);
    }

    const bool diag = (k0 + 127 > q0);
    const int qr0 = q0 + m0 + g, qr1 = qr0 + 8;
#pragma unroll
    for (int ni = 0; ni < 16; ni++) {
      float v0 = sacc[ni][0] * qk_scale;
      float v1 = sacc[ni][1] * qk_scale;
      float v2 = sacc[ni][2] * qk_scale;
      float v3 = sacc[ni][3] * qk_scale;
      if (diag) {
        int kc = k0 + ni * 8 + 2 * t4;
        if (kc > qr0) v0 = -1e30f;
        if (kc + 1 > qr0) v1 = -1e30f;
        if (kc > qr1) v2 = -1e30f;
        if (kc + 1 > qr1) v3 = -1e30f;
      }
      sacc[ni][0] = v0; sacc[ni][1] = v1; sacc[ni][2] = v2; sacc[ni][3] = v3;
    }

    float mx0 = -INFINITY, mx1 = -INFINITY;
#pragma unroll
    for (int ni = 0; ni < 16; ni++) {
      mx0 = fmaxf(mx0, fmaxf(sacc[ni][0], sacc[ni][1]));
      mx1 = fmaxf(mx1, fmaxf(sacc[ni][2], sacc[ni][3]));
    }
    mx0 = fmaxf(mx0, __shfl_xor_sync(0xffffffffu, mx0, 1));
    mx0 = fmaxf(mx0, __shfl_xor_sync(0xffffffffu, mx0, 2));
    mx1 = fmaxf(mx1, __shfl_xor_sync(0xffffffffu, mx1, 1));
    mx1 = fmaxf(mx1, __shfl_xor_sync(0xffffffffu, mx1, 2));
    const float mn0 = fmaxf(m0r, mx0);
    const float mn1 = fmaxf(m1r, mx1);

    uint32_t ph0[16], ph1[16];
    float s0 = 0.f, s1 = 0.f;
#pragma unroll
    for (int ni = 0; ni < 16; ni++) {
      __half2 e01 = __floats2half2_rn(__expf(sacc[ni][0] - mn0),
                                      __expf(sacc[ni][1] - mn0));
      __half2 e23 = __floats2half2_rn(__expf(sacc[ni][2] - mn1),
                                      __expf(sacc[ni][3] - mn1));
      ph0[ni] = *(uint32_t*)&e01;
      ph1[ni] = *(uint32_t*)&e23;
      float2 f01 = __half22float2(e01);
      float2 f23 = __half22float2(e23);
      s0 += f01.x + f01.y;
      s1 += f23.x + f23.y;
    }
    s0 += __shfl_xor_sync(0xffffffffu, s0, 1);
    s0 += __shfl_xor_sync(0xffffffffu, s0, 2);
    s1 += __shfl_xor_sync(0xffffffffu, s1, 1);
    s1 += __shfl_xor_sync(0xffffffffu, s1, 2);
    const float al0 = __expf(m0r - mn0);
    const float al1 = __expf(m1r - mn1);
    m0r = mn0; m1r = mn1;
    l0r = l0r * al0 + s0;
    l1r = l1r * al1 + s1;
#pragma unroll
    for (int ni = 0; ni < 16; ni++) {
      oacc[ni][0] *= al0;
      oacc[ni][1] *= al0;
      oacc[ni][2] *= al1;
      oacc[ni][3] *= al1;
    }

    CP_WAIT2();
    __syncthreads();

    if (t + 2 < T) attn_issue_k(tid, kb + (size_t)(k0 + 256) * KN,
                                Ks + (t & 1) * KS_SZ);
    CP_COMMIT();

#pragma unroll
    for (int ks = 0; ks < 8; ks++) {
      const int kk = ks * 16;
      uint32_t a[4];
      a[0] = ph0[2 * ks];
      a[1] = ph1[2 * ks];
      a[2] = ph0[2 * ks + 1];
      a[3] = ph1[2 * ks + 1];
      uint32_t bfr[16][2];
#pragma unroll
      for (int nip = 0; nip < 8; nip++) {
        uint32_t bd = vsu + ((nip * 16 + b_lrow) * VT_STRIDE + kk + b_koff) * 2;
        LDSM4(bfr[2 * nip][0], bfr[2 * nip][1], bfr[2 * nip + 1][0],
              bfr[2 * nip + 1][1], bd);
      }
#pragma unroll
      for (int ni = 0; ni < 16; ni++) MMA_F16(oacc[ni], a, bfr[ni]);
    }
    __syncthreads();

    if (t + 2 < T) attn_issue_v(tid, vtb + k0 + 256, Vs + (t & 1) * VS_SZ);
    CP_COMMIT();
  }

  {
    const float inv0 = 1.f / l0r;
    const float inv1 = 1.f / l1r;
    __half* o0 = O + (size_t)(b * S + q0 + m0 + g) * QN + h * HD + 2 * t4;
    __half* o1 = o0 + (size_t)8 * QN;
#pragma unroll
    for (int ni = 0; ni < 16; ni++) {
      *(__half2*)(o0 + ni * 8) =
          __floats2half2_rn(oacc[ni][0] * inv0, oacc[ni][1] * inv0);
      *(__half2*)(o1 + ni * 8) =
          __floats2half2_rn(oacc[ni][2] * inv1, oacc[ni][3] * inv1);
    }
  }
}

// ---------------------------------------------------------------------------
extern "C" void kernel_launch(void* const* d_in, const int* in_sizes, int n_in,
                              void* d_out, int out_size) {
  const float* x  = (const float*)d_in[0];
  const float* Wq = (const float*)d_in[1];
  const float* Wk = (const float*)d_in[2];
  const float* Wv = (const float*)d_in[3];
  const float* Wo = (const float*)d_in[4];
  float* out = (float*)d_out;

  __half *xh, *wqT, *wkT, *wvT, *woT, *qh, *kh, *vT, *attnh;
  cudaGetSymbolAddress((void**)&xh, g_xh);
  cudaGetSymbolAddress((void**)&wqT, g_wqT);
  cudaGetSymbolAddress((void**)&wkT, g_wkT);
  cudaGetSymbolAddress((void**)&wvT, g_wvT);
  cudaGetSymbolAddress((void**)&woT, g_woT);
  cudaGetSymbolAddress((void**)&qh, g_qh);
  cudaGetSymbolAddress((void**)&kh, g_kh);
  cudaGetSymbolAddress((void**)&vT, g_vT);
  cudaGetSymbolAddress((void**)&attnh, g_attnh);

  cudaFuncSetAttribute(qkv_gemm, cudaFuncAttributeMaxDynamicSharedMemorySize,
                       GEMM_SMEM_BYTES);
  cudaFuncSetAttribute(o_gemm, cudaFuncAttributeMaxDynamicSharedMemorySize,
                       GEMM_SMEM_BYTES);
  cudaFuncSetAttribute(attn_kernel, cudaFuncAttributeMaxDynamicSharedMemorySize,
                       ATTN_SMEM_BYTES);

  conv_half<<<(M_ROWS * D / 4 + 255) / 256, 256>>>(x, xh, M_ROWS * D / 4);
  transpose_all<<<dim3(64, 64, 4), dim3(32, 8)>>>(Wq, Wk, Wv, Wo,
                                                  wqT, wkT, wvT, woT);

  qkv_gemm<<<dim3(24, M_ROWS / 128), 128, GEMM_SMEM_BYTES>>>(xh, wqT, wkT, wvT,
                                                             qh, kh, vT);
  attn_kernel<<<dim3(S / 128, B * H), 256, ATTN_SMEM_BYTES>>>(qh, kh, vT, attnh);
  o_gemm<<<dim3(D / 128, M_ROWS / 128), 128, GEMM_SMEM_BYTES>>>(attnh, woT, out);
}

// round 15
// speedup vs baseline: 1.0339x; 1.0339x over previous
#include <cuda_runtime.h>
#include <cuda_fp16.h>
#include <math.h>
#include <stdint.h>

#define B 2
#define S 2048
#define D 2048
#define H 16
#define HKV 4
#define HD 128
#define M_ROWS (B*S)     // 4096
#define QN (H*HD)        // 2048
#define KN (HKV*HD)      // 512

// Scratch (allocation-free: device globals), fp16 operands everywhere
__device__ __half g_xh[(size_t)M_ROWS * D];
__device__ __half g_wqT[(size_t)QN * D];    // [N][K]
__device__ __half g_wkT[(size_t)KN * D];
__device__ __half g_wvT[(size_t)KN * D];
__device__ __half g_woT[(size_t)D * QN];
__device__ __half g_qh[(size_t)M_ROWS * QN];
__device__ __half g_kh[(size_t)M_ROWS * KN];
__device__ __half g_vT[(size_t)B * HKV * HD * S];  // [b][hk][d][s]
__device__ __half g_attnh[(size_t)M_ROWS * QN];

#define MMA_F16(c, a, b)                                                      \
  asm("mma.sync.aligned.m16n8k16.row.col.f32.f16.f16.f32 "                    \
      "{%0,%1,%2,%3},{%4,%5,%6,%7},{%8,%9},{%0,%1,%2,%3};"                    \
      : "+f"(c[0]), "+f"(c[1]), "+f"(c[2]), "+f"(c[3])                        \
      : "r"(a[0]), "r"(a[1]), "r"(a[2]), "r"(a[3]), "r"(b[0]), "r"(b[1]))

#define LDSM4(r0, r1, r2, r3, addr)                                           \
  asm volatile("ldmatrix.sync.aligned.m8n8.x4.shared.b16 {%0,%1,%2,%3}, [%4];"\
               : "=r"(r0), "=r"(r1), "=r"(r2), "=r"(r3) : "r"(addr))

#define CP16(dst, src)                                                        \
  asm volatile("cp.async.cg.shared.global [%0], [%1], 16;" ::"r"(dst), "l"(src))
#define CP_COMMIT() asm volatile("cp.async.commit_group;")
#define CP_WAIT1()  asm volatile("cp.async.wait_group 1;")

// ---------------------------------------------------------------------------
// fp32 -> fp16 convert (x), batched tiled transpose+convert (all 4 weights)
// ---------------------------------------------------------------------------
__global__ void conv_half(const float* __restrict__ src,
                          __half* __restrict__ dst, int n4) {
  int i = blockIdx.x * blockDim.x + threadIdx.x;
  if (i < n4) {
    float4 v = *(const float4*)(src + 4 * (size_t)i);
    *(__half2*)(dst + 4 * (size_t)i) = __floats2half2_rn(v.x, v.y);
    *(__half2*)(dst + 4 * (size_t)i + 2) = __floats2half2_rn(v.z, v.w);
  }
}

__global__ void transpose_all(const float* __restrict__ Wq,
                              const float* __restrict__ Wk,
                              const float* __restrict__ Wv,
                              const float* __restrict__ Wo,
                              __half* __restrict__ wqT, __half* __restrict__ wkT,
                              __half* __restrict__ wvT, __half* __restrict__ woT) {
  __shared__ float t[32][33];
  const float* src;
  __half* dst;
  int R, C;
  switch (blockIdx.z) {
    case 0: src = Wq; dst = wqT; R = D;  C = QN; break;
    case 1: src = Wk; dst = wkT; R = D;  C = KN; break;
    case 2: src = Wv; dst = wvT; R = D;  C = KN; break;
    default: src = Wo; dst = woT; R = QN; C = D;  break;
  }
  int c0 = blockIdx.x * 32, r0 = blockIdx.y * 32;
  if (c0 >= C || r0 >= R) return;
  int x = threadIdx.x, y = threadIdx.y;
#pragma unroll
  for (int i = 0; i < 32; i += 8)
    t[y + i][x] = src[(size_t)(r0 + y + i) * C + c0 + x];
  __syncthreads();
#pragma unroll
  for (int i = 0; i < 32; i += 8)
    dst[(size_t)(c0 + y + i) * R + r0 + x] = __float2half_rn(t[x][y + i]);
}

// ---------------------------------------------------------------------------
// fp16 MMA GEMM: 128x128x32 block tile, 128 threads (4 warps, warp 64x64),
// 3-buffer single-barrier cp.async pipeline, ldmatrix fragments, 3 CTAs/SM.
// Epilogues: 0 half, 1 V^T half, 2 fp32, 3 half + fused RoPE (Q/K proj).
// ---------------------------------------------------------------------------
#define AS_STRIDE 40
#define BS_STRIDE 40
#define AS_SZ (128 * AS_STRIDE)
#define BS_SZ (128 * BS_STRIDE)
#define GEMM_SMEM_BYTES (3 * (AS_SZ + BS_SZ) * 2)

__device__ __forceinline__ void gemm_issue_slab(
    int tid, const __half* __restrict__ A, const __half* __restrict__ BT,
    int K, int row0, int col0, int k0, __half* as, __half* bs) {
#pragma unroll
  for (int l = 0; l < 4; l++) {
    int idx = tid + l * 128;
    int ar = idx >> 2, ac = (idx & 3) << 3;
    const __half* asrc = A + (size_t)(row0 + ar) * K + k0 + ac;
    uint32_t adst = (uint32_t)__cvta_generic_to_shared(as + ar * AS_STRIDE + ac);
    CP16(adst, asrc);
  }
#pragma unroll
  for (int l = 0; l < 4; l++) {
    int idx = tid + l * 128;
    int br = idx >> 2, bc = (idx & 3) << 3;
    const __half* bsrc = BT + (size_t)(col0 + br) * K + k0 + bc;
    uint32_t bdst = (uint32_t)__cvta_generic_to_shared(bs + br * BS_STRIDE + bc);
    CP16(bdst, bsrc);
  }
}

template <int MODE>
__device__ __forceinline__ void gemm_body(
    const __half* __restrict__ A, const __half* __restrict__ BT,
    void* __restrict__ Cv, int N, int K, int row0, int col0, __half* smp,
    int vb_base) {
  __half* As = smp;                 // 3 x [128][40]
  __half* Bs = smp + 3 * AS_SZ;     // 3 x [128][40]

  const int tid = threadIdx.x;
  const int lane = tid & 31;
  const int w = tid >> 5;
  const int g = lane >> 2;
  const int t4 = lane & 3;
  const int warp_m = w & 1, warp_n = w >> 1;
  const int m0w = warp_m * 64, n0w = warp_n * 64;

  const int a_lrow = (lane & 7) + ((lane >> 3) & 1) * 8;
  const int a_koff = (lane >> 4) * 8;
  const int b_lrow = (lane & 7) + (lane >> 4) * 8;
  const int b_koff = ((lane >> 3) & 1) * 8;

  float acc[4][8][4];
#pragma unroll
  for (int mi = 0; mi < 4; mi++)
#pragma unroll
    for (int ni = 0; ni < 8; ni++)
#pragma unroll
      for (int e = 0; e < 4; e++) acc[mi][ni][e] = 0.f;

  gemm_issue_slab(tid, A, BT, K, row0, col0, 0, As, Bs);
  CP_COMMIT();
  gemm_issue_slab(tid, A, BT, K, row0, col0, 32, As + AS_SZ, Bs + BS_SZ);
  CP_COMMIT();

  const uint32_t asu0 = (uint32_t)__cvta_generic_to_shared(As);
  const uint32_t bsu0 = (uint32_t)__cvta_generic_to_shared(Bs);

  const int nslab = K >> 5;
  for (int it = 0; it < nslab; it++) {
    CP_WAIT1();
    __syncthreads();
    int kn = it + 2;
    if (kn < nslab)
      gemm_issue_slab(tid, A, BT, K, row0, col0, kn << 5,
                      As + (kn % 3) * AS_SZ, Bs + (kn % 3) * BS_SZ);
    CP_COMMIT();

    const uint32_t asu = asu0 + (it % 3) * AS_SZ * 2;
    const uint32_t bsu = bsu0 + (it % 3) * BS_SZ * 2;
#pragma unroll
    for (int ks = 0; ks < 2; ks++) {
      const int kk = ks * 16;
      uint32_t a[4][4];
#pragma unroll
      for (int mi = 0; mi < 4; mi++) {
        uint32_t ad = asu +
            ((m0w + mi * 16 + a_lrow) * AS_STRIDE + kk + a_koff) * 2;
        LDSM4(a[mi][0], a[mi][1], a[mi][2], a[mi][3], ad);
      }
      uint32_t b[8][2];
#pragma unroll
      for (int nip = 0; nip < 4; nip++) {
        uint32_t bd = bsu +
            ((n0w + nip * 16 + b_lrow) * BS_STRIDE + kk + b_koff) * 2;
        LDSM4(b[2 * nip][0], b[2 * nip][1], b[2 * nip + 1][0],
              b[2 * nip + 1][1], bd);
      }
#pragma unroll
      for (int mi = 0; mi < 4; mi++)
#pragma unroll
        for (int ni = 0; ni < 8; ni++) MMA_F16(acc[mi][ni], a[mi], b[ni]);
    }
  }

#pragma unroll
  for (int mi = 0; mi < 4; mi++) {
    int r0 = row0 + m0w + mi * 16 + g;
#pragma unroll
    for (int ni = 0; ni < 8; ni++) {
      int col = col0 + n0w + ni * 8 + 2 * t4;
      if (MODE == 0) {
        __half* C = (__half*)Cv;
        *(__half2*)(C + (size_t)r0 * N + col) =
            __floats2half2_rn(acc[mi][ni][0], acc[mi][ni][1]);
        *(__half2*)(C + (size_t)(r0 + 8) * N + col) =
            __floats2half2_rn(acc[mi][ni][2], acc[mi][ni][3]);
      } else if (MODE == 1) {
        __half* C = (__half*)Cv;
        int s0 = r0 & (S - 1);
        int b0 = r0 >> 11;
        int d = col & (HD - 1);
        __half* base = C + ((size_t)(b0 * HKV) + vb_base) * HD * S;
        base[(size_t)d * S + s0] = __float2half_rn(acc[mi][ni][0]);
        base[(size_t)(d + 1) * S + s0] = __float2half_rn(acc[mi][ni][1]);
        base[(size_t)d * S + s0 + 8] = __float2half_rn(acc[mi][ni][2]);
        base[(size_t)(d + 1) * S + s0 + 8] = __float2half_rn(acc[mi][ni][3]);
      } else if (MODE == 2) {
        float* C = (float*)Cv;
        *(float2*)(C + (size_t)r0 * N + col) =
            make_float2(acc[mi][ni][0], acc[mi][ni][1]);
        *(float2*)(C + (size_t)(r0 + 8) * N + col) =
            make_float2(acc[mi][ni][2], acc[mi][ni][3]);
      } else {  // MODE 3: fused RoPE. Thread holds cols (2j, 2j+1) of one head.
        __half* C = (__half*)Cv;
        const int s0 = r0 & (S - 1);
        const int jj = (col & 127) >> 1;
        const int cb = col - (col & 127);
        const float theta = exp2f(-(float)jj * 0.20762050593045983f);
        float sn0, cs0, sn1, cs1;
        sincosf((float)s0 * theta, &sn0, &cs0);
        sincosf((float)(s0 + 8) * theta, &sn1, &cs1);
        __half* p0 = C + (size_t)r0 * N + cb + jj;
        __half* p1 = C + (size_t)(r0 + 8) * N + cb + jj;
        p0[0]  = __float2half_rn(acc[mi][ni][0] * cs0 - acc[mi][ni][1] * sn0);
        p0[64] = __float2half_rn(acc[mi][ni][0] * sn0 + acc[mi][ni][1] * cs0);
        p1[0]  = __float2half_rn(acc[mi][ni][2] * cs1 - acc[mi][ni][3] * sn1);
        p1[64] = __float2half_rn(acc[mi][ni][2] * sn1 + acc[mi][ni][3] * cs1);
      }
    }
  }
}

__global__ void __launch_bounds__(128, 3)
qkv_gemm(const __half* __restrict__ xh, const __half* __restrict__ wqT,
         const __half* __restrict__ wkT, const __half* __restrict__ wvT,
         __half* __restrict__ q, __half* __restrict__ k,
         __half* __restrict__ vT) {
  extern __shared__ __half smp[];
  const int bx = blockIdx.x;
  const int row0 = blockIdx.y * 128;
  if (bx < 16) {
    gemm_body<3>(xh, wqT, q, QN, D, row0, bx * 128, smp, 0);        // Q + RoPE
  } else if (bx < 20) {
    gemm_body<3>(xh, wkT, k, KN, D, row0, (bx - 16) * 128, smp, 0); // K + RoPE
  } else {
    int col0 = (bx - 20) * 128;
    gemm_body<1>(xh, wvT, vT, KN, D, row0, col0, smp, col0 >> 7);
  }
}

__global__ void __launch_bounds__(128, 3)
o_gemm(const __half* __restrict__ attnh, const __half* __restrict__ woT,
       float* __restrict__ out) {
  extern __shared__ __half smp[];
  gemm_body<2>(attnh, woT, out, D, QN, blockIdx.y * 128, blockIdx.x * 128, smp, 0);
}

// ---------------------------------------------------------------------------
// Flash attention (R12 verbatim): 128 threads (4 warps x 16 q-rows = 64 rows),
// k-tile 128, single-buffered K/V with phase-overlapped prefetch.
// ---------------------------------------------------------------------------
#define QS_STRIDE 136
#define KS_STRIDE 136
#define VT_STRIDE 136
#define ATTN_SMEM_BYTES ((64 * QS_STRIDE + 128 * KS_STRIDE + 128 * VT_STRIDE) * 2)

__device__ __forceinline__ void attn_issue_k(int tid, const __half* src,
                                             __half* dst) {
#pragma unroll
  for (int i = 0; i < 16; i++) {
    int idx = tid + i * 128;
    int n = idx >> 4, c8 = (idx & 15) << 3;
    uint32_t d = (uint32_t)__cvta_generic_to_shared(dst + n * KS_STRIDE + c8);
    CP16(d, src + (size_t)n * KN + c8);
  }
}
__device__ __forceinline__ void attn_issue_v(int tid, const __half* src,
                                             __half* dst) {
#pragma unroll
  for (int i = 0; i < 16; i++) {
    int idx = tid + i * 128;
    int dd = idx >> 4, c8 = (idx & 15) << 3;
    uint32_t d = (uint32_t)__cvta_generic_to_shared(dst + dd * VT_STRIDE + c8);
    CP16(d, src + (size_t)dd * S + c8);
  }
}

__global__ void __launch_bounds__(128, 2)
attn_kernel(const __half* __restrict__ Q, const __half* __restrict__ K,
            const __half* __restrict__ VT, __half* __restrict__ O) {
  extern __shared__ __half smh[];
  __half* Qs = smh;                      // [64][136]
  __half* Ks = Qs + 64 * QS_STRIDE;      // [128][136]
  __half* Vs = Ks + 128 * KS_STRIDE;     // [128][136] (V^T)

  const int tid = threadIdx.x;
  const int lane = tid & 31;
  const int w = tid >> 5;                // 0..3
  const int g = lane >> 2;
  const int t4 = lane & 3;
  const int m0 = w * 16;

  const int a_lrow = (lane & 7) + ((lane >> 3) & 1) * 8;
  const int a_koff = (lane >> 4) * 8;
  const int b_lrow = (lane & 7) + (lane >> 4) * 8;
  const int b_koff = ((lane >> 3) & 1) * 8;

  const uint32_t qsu = (uint32_t)__cvta_generic_to_shared(Qs);
  const uint32_t ksu = (uint32_t)__cvta_generic_to_shared(Ks);
  const uint32_t vsu = (uint32_t)__cvta_generic_to_shared(Vs);

  const int qi = (int)gridDim.x - 1 - (int)blockIdx.x;  // heavy tiles first
  const int bh = blockIdx.y;
  const int b = bh >> 4;
  const int h = bh & 15;
  const int hk = h >> 2;
  const int q0 = qi * 64;

  const __half* qb = Q + (size_t)b * S * QN + h * HD;
  const __half* kb = K + (size_t)b * S * KN + hk * HD;
  const __half* vtb = VT + ((size_t)(b * HKV + hk)) * HD * S;

  const int T = (q0 >> 7) + 1;

  // Prologue: G1 = Q + K0, G2 = V0
#pragma unroll
  for (int i = 0; i < 8; i++) {
    int idx = tid + i * 128;
    int r = idx >> 4, c8 = (idx & 15) << 3;
    uint32_t d = (uint32_t)__cvta_generic_to_shared(Qs + r * QS_STRIDE + c8);
    CP16(d, qb + (size_t)(q0 + r) * QN + c8);
  }
  attn_issue_k(tid, kb, Ks);
  CP_COMMIT();
  attn_issue_v(tid, vtb, Vs);
  CP_COMMIT();

  float oacc[16][4];
#pragma unroll
  for (int ni = 0; ni < 16; ni++)
#pragma unroll
    for (int e = 0; e < 4; e++) oacc[ni][e] = 0.f;

  float m0r = -INFINITY, m1r = -INFINITY;
  float l0r = 0.f, l1r = 0.f;

  const float qk_scale = 0.08838834764831845f;

  for (int t = 0; t < T; t++) {
    const int k0 = t << 7;

    CP_WAIT1();         // K_t (and Q on t=0) ready; V_t may be in flight
    __syncthreads();

    // ---- scores: 16 rows x 128 cols, k = 128 ----
    float sacc[16][4];
#pragma unroll
    for (int ni = 0; ni < 16; ni++)
#pragma unroll
      for (int e = 0; e < 4; e++) sacc[ni][e] = 0.f;

#pragma unroll
    for (int ks = 0; ks < 8; ks++) {
      const int kk = ks * 16;
      uint32_t a[4];
      uint32_t ad = qsu + ((m0 + a_lrow) * QS_STRIDE + kk + a_koff) * 2;
      LDSM4(a[0], a[1], a[2], a[3], ad);
      uint32_t bfr[16][2];
#pragma unroll
      for (int nip = 0; nip < 8; nip++) {
        uint32_t bd = ksu + ((nip * 16 + b_lrow) * KS_STRIDE + kk + b_koff) * 2;
        LDSM4(bfr[2 * nip][0], bfr[2 * nip][1], bfr[2 * nip + 1][0],
              bfr[2 * nip + 1][1], bd);
      }
#pragma unroll
      for (int ni = 0; ni < 16; ni++) MMA_F16(sacc[ni], a, bfr[ni]);
    }
    __syncthreads();    // all warps done reading Ks

    // Prefetch K_{t+1} (overlaps softmax below + PV)
    if (t + 1 < T) attn_issue_k(tid, kb + (size_t)(k0 + 128) * KN, Ks);
    CP_COMMIT();

    // ---- scale + causal mask (registers) ----
    const bool diag = (k0 + 127 > q0);
    const int qr0 = q0 + m0 + g, qr1 = qr0 + 8;
#pragma unroll
    for (int ni = 0; ni < 16; ni++) {
      float v0 = sacc[ni][0] * qk_scale;
      float v1 = sacc[ni][1] * qk_scale;
      float v2 = sacc[ni][2] * qk_scale;
      float v3 = sacc[ni][3] * qk_scale;
      if (diag) {
        int kc = k0 + ni * 8 + 2 * t4;
        if (kc > qr0) v0 = -1e30f;
        if (kc + 1 > qr0) v1 = -1e30f;
        if (kc > qr1) v2 = -1e30f;
        if (kc + 1 > qr1) v3 = -1e30f;
      }
      sacc[ni][0] = v0; sacc[ni][1] = v1; sacc[ni][2] = v2; sacc[ni][3] = v3;
    }

    // ---- register softmax (rows g, g+8; reduce across quad t4) ----
    float mx0 = -INFINITY, mx1 = -INFINITY;
#pragma unroll
    for (int ni = 0; ni < 16; ni++) {
      mx0 = fmaxf(mx0, fmaxf(sacc[ni][0], sacc[ni][1]));
      mx1 = fmaxf(mx1, fmaxf(sacc[ni][2], sacc[ni][3]));
    }
    mx0 = fmaxf(mx0, __shfl_xor_sync(0xffffffffu, mx0, 1));
    mx0 = fmaxf(mx0, __shfl_xor_sync(0xffffffffu, mx0, 2));
    mx1 = fmaxf(mx1, __shfl_xor_sync(0xffffffffu, mx1, 1));
    mx1 = fmaxf(mx1, __shfl_xor_sync(0xffffffffu, mx1, 2));
    const float mn0 = fmaxf(m0r, mx0);
    const float mn1 = fmaxf(m1r, mx1);

    uint32_t ph0[16], ph1[16];
    float s0 = 0.f, s1 = 0.f;
#pragma unroll
    for (int ni = 0; ni < 16; ni++) {
      __half2 e01 = __floats2half2_rn(__expf(sacc[ni][0] - mn0),
                                      __expf(sacc[ni][1] - mn0));
      __half2 e23 = __floats2half2_rn(__expf(sacc[ni][2] - mn1),
                                      __expf(sacc[ni][3] - mn1));
      ph0[ni] = *(uint32_t*)&e01;
      ph1[ni] = *(uint32_t*)&e23;
      float2 f01 = __half22float2(e01);
      float2 f23 = __half22float2(e23);
      s0 += f01.x + f01.y;
      s1 += f23.x + f23.y;
    }
    s0 += __shfl_xor_sync(0xffffffffu, s0, 1);
    s0 += __shfl_xor_sync(0xffffffffu, s0, 2);
    s1 += __shfl_xor_sync(0xffffffffu, s1, 1);
    s1 += __shfl_xor_sync(0xffffffffu, s1, 2);
    const float al0 = __expf(m0r - mn0);
    const float al1 = __expf(m1r - mn1);
    m0r = mn0; m1r = mn1;
    l0r = l0r * al0 + s0;
    l1r = l1r * al1 + s1;
#pragma unroll
    for (int ni = 0; ni < 16; ni++) {
      oacc[ni][0] *= al0;
      oacc[ni][1] *= al0;
      oacc[ni][2] *= al1;
      oacc[ni][3] *= al1;
    }

    CP_WAIT1();         // V_t ready (K_{t+1} may remain in flight)
    __syncthreads();

    // ---- PV: A from registers (ph), B = V^T tiles from smem, k = 128 ----
#pragma unroll
    for (int ks = 0; ks < 8; ks++) {
      const int kk = ks * 16;
      uint32_t a[4];
      a[0] = ph0[2 * ks];
      a[1] = ph1[2 * ks];
      a[2] = ph0[2 * ks + 1];
      a[3] = ph1[2 * ks + 1];
      uint32_t bfr[16][2];
#pragma unroll
      for (int nip = 0; nip < 8; nip++) {
        uint32_t bd = vsu + ((nip * 16 + b_lrow) * VT_STRIDE + kk + b_koff) * 2;
        LDSM4(bfr[2 * nip][0], bfr[2 * nip][1], bfr[2 * nip + 1][0],
              bfr[2 * nip + 1][1], bd);
      }
#pragma unroll
      for (int ni = 0; ni < 16; ni++) MMA_F16(oacc[ni], a, bfr[ni]);
    }
    __syncthreads();    // all warps done reading Vs

    // Prefetch V_{t+1} (overlaps next scores)
    if (t + 1 < T) attn_issue_v(tid, vtb + k0 + 128, Vs);
    CP_COMMIT();
  }

  // ---- finalize: O = half(oacc / l) ----
  {
    const float inv0 = 1.f / l0r;
    const float inv1 = 1.f / l1r;
    __half* o0 = O + (size_t)(b * S + q0 + m0 + g) * QN + h * HD + 2 * t4;
    __half* o1 = o0 + (size_t)8 * QN;
#pragma unroll
    for (int ni = 0; ni < 16; ni++) {
      *(__half2*)(o0 + ni * 8) =
          __floats2half2_rn(oacc[ni][0] * inv0, oacc[ni][1] * inv0);
      *(__half2*)(o1 + ni * 8) =
          __floats2half2_rn(oacc[ni][2] * inv1, oacc[ni][3] * inv1);
    }
  }
}

// ---------------------------------------------------------------------------
extern "C" void kernel_launch(void* const* d_in, const int* in_sizes, int n_in,
                              void* d_out, int out_size) {
  const float* x  = (const float*)d_in[0];
  const float* Wq = (const float*)d_in[1];
  const float* Wk = (const float*)d_in[2];
  const float* Wv = (const float*)d_in[3];
  const float* Wo = (const float*)d_in[4];
  float* out = (float*)d_out;

  __half *xh, *wqT, *wkT, *wvT, *woT, *qh, *kh, *vT, *attnh;
  cudaGetSymbolAddress((void**)&xh, g_xh);
  cudaGetSymbolAddress((void**)&wqT, g_wqT);
  cudaGetSymbolAddress((void**)&wkT, g_wkT);
  cudaGetSymbolAddress((void**)&wvT, g_wvT);
  cudaGetSymbolAddress((void**)&woT, g_woT);
  cudaGetSymbolAddress((void**)&qh, g_qh);
  cudaGetSymbolAddress((void**)&kh, g_kh);
  cudaGetSymbolAddress((void**)&vT, g_vT);
  cudaGetSymbolAddress((void**)&attnh, g_attnh);

  cudaFuncSetAttribute(qkv_gemm, cudaFuncAttributeMaxDynamicSharedMemorySize,
                       GEMM_SMEM_BYTES);
  cudaFuncSetAttribute(o_gemm, cudaFuncAttributeMaxDynamicSharedMemorySize,
                       GEMM_SMEM_BYTES);
  cudaFuncSetAttribute(attn_kernel, cudaFuncAttributeMaxDynamicSharedMemorySize,
                       ATTN_SMEM_BYTES);

  conv_half<<<(M_ROWS * D / 4 + 255) / 256, 256>>>(x, xh, M_ROWS * D / 4);
  transpose_all<<<dim3(64, 64, 4), dim3(32, 8)>>>(Wq, Wk, Wv, Wo,
                                                  wqT, wkT, wvT, woT);

  qkv_gemm<<<dim3(24, M_ROWS / 128), 128, GEMM_SMEM_BYTES>>>(xh, wqT, wkT, wvT,
                                                             qh, kh, vT);
  attn_kernel<<<dim3(S / 64, B * H), 128, ATTN_SMEM_BYTES>>>(qh, kh, vT, attnh);
  o_gemm<<<dim3(D / 128, M_ROWS / 128), 128, GEMM_SMEM_BYTES>>>(attnh, woT, out);
}

// round 16
// speedup vs baseline: 1.0460x; 1.0116x over previous
#include <cuda_runtime.h>
#include <cuda_fp16.h>
#include <math.h>
#include <stdint.h>

#define B 2
#define S 2048
#define D 2048
#define H 16
#define HKV 4
#define HD 128
#define M_ROWS (B*S)     // 4096
#define QN (H*HD)        // 2048
#define KN (HKV*HD)      // 512

// Scratch (allocation-free: device globals), fp16 operands everywhere
__device__ __half g_xh[(size_t)M_ROWS * D];
__device__ __half g_wqT[(size_t)QN * D];    // [N][K]
__device__ __half g_wkT[(size_t)KN * D];
__device__ __half g_wvT[(size_t)KN * D];
__device__ __half g_woT[(size_t)D * QN];
__device__ __half g_qh[(size_t)M_ROWS * QN];
__device__ __half g_kh[(size_t)M_ROWS * KN];
__device__ __half g_vT[(size_t)B * HKV * HD * S];  // [b][hk][d][s]
__device__ __half g_attnh[(size_t)M_ROWS * QN];

#define MMA_F16(c, a, b)                                                      \
  asm("mma.sync.aligned.m16n8k16.row.col.f32.f16.f16.f32 "                    \
      "{%0,%1,%2,%3},{%4,%5,%6,%7},{%8,%9},{%0,%1,%2,%3};"                    \
      : "+f"(c[0]), "+f"(c[1]), "+f"(c[2]), "+f"(c[3])                        \
      : "r"(a[0]), "r"(a[1]), "r"(a[2]), "r"(a[3]), "r"(b[0]), "r"(b[1]))

#define LDSM4(r0, r1, r2, r3, addr)                                           \
  asm volatile("ldmatrix.sync.aligned.m8n8.x4.shared.b16 {%0,%1,%2,%3}, [%4];"\
               : "=r"(r0), "=r"(r1), "=r"(r2), "=r"(r3) : "r"(addr))

#define CP16(dst, src)                                                        \
  asm volatile("cp.async.cg.shared.global [%0], [%1], 16;" ::"r"(dst), "l"(src))
#define CP_COMMIT() asm volatile("cp.async.commit_group;")
#define CP_WAIT1()  asm volatile("cp.async.wait_group 1;")

// ---------------------------------------------------------------------------
// fp32 -> fp16 convert (x), batched tiled transpose+convert (all 4 weights)
// ---------------------------------------------------------------------------
__global__ void conv_half(const float* __restrict__ src,
                          __half* __restrict__ dst, int n4) {
  int i = blockIdx.x * blockDim.x + threadIdx.x;
  if (i < n4) {
    float4 v = *(const float4*)(src + 4 * (size_t)i);
    *(__half2*)(dst + 4 * (size_t)i) = __floats2half2_rn(v.x, v.y);
    *(__half2*)(dst + 4 * (size_t)i + 2) = __floats2half2_rn(v.z, v.w);
  }
}

__global__ void transpose_all(const float* __restrict__ Wq,
                              const float* __restrict__ Wk,
                              const float* __restrict__ Wv,
                              const float* __restrict__ Wo,
                              __half* __restrict__ wqT, __half* __restrict__ wkT,
                              __half* __restrict__ wvT, __half* __restrict__ woT) {
  __shared__ float t[32][33];
  const float* src;
  __half* dst;
  int R, C;
  switch (blockIdx.z) {
    case 0: src = Wq; dst = wqT; R = D;  C = QN; break;
    case 1: src = Wk; dst = wkT; R = D;  C = KN; break;
    case 2: src = Wv; dst = wvT; R = D;  C = KN; break;
    default: src = Wo; dst = woT; R = QN; C = D;  break;
  }
  int c0 = blockIdx.x * 32, r0 = blockIdx.y * 32;
  if (c0 >= C || r0 >= R) return;
  int x = threadIdx.x, y = threadIdx.y;
#pragma unroll
  for (int i = 0; i < 32; i += 8)
    t[y + i][x] = src[(size_t)(r0 + y + i) * C + c0 + x];
  __syncthreads();
#pragma unroll
  for (int i = 0; i < 32; i += 8)
    dst[(size_t)(c0 + y + i) * R + r0 + x] = __float2half_rn(t[x][y + i]);
}

// ---------------------------------------------------------------------------
// fp16 MMA GEMM: 128x128x32 block tile, 128 threads (4 warps, warp 64x64),
// 3-buffer single-barrier cp.async pipeline, ldmatrix fragments, 2 CTAs/SM.
// Epilogues: 0 half, 1 V^T half, 2 fp32, 3 half + fused RoPE (Q/K proj).
// ---------------------------------------------------------------------------
#define AS_STRIDE 40
#define BS_STRIDE 40
#define AS_SZ (128 * AS_STRIDE)
#define BS_SZ (128 * BS_STRIDE)
#define GEMM_SMEM_BYTES (3 * (AS_SZ + BS_SZ) * 2)

__device__ __forceinline__ void gemm_issue_slab(
    int tid, const __half* __restrict__ A, const __half* __restrict__ BT,
    int K, int row0, int col0, int k0, __half* as, __half* bs) {
#pragma unroll
  for (int l = 0; l < 4; l++) {
    int idx = tid + l * 128;
    int ar = idx >> 2, ac = (idx & 3) << 3;
    const __half* asrc = A + (size_t)(row0 + ar) * K + k0 + ac;
    uint32_t adst = (uint32_t)__cvta_generic_to_shared(as + ar * AS_STRIDE + ac);
    CP16(adst, asrc);
  }
#pragma unroll
  for (int l = 0; l < 4; l++) {
    int idx = tid + l * 128;
    int br = idx >> 2, bc = (idx & 3) << 3;
    const __half* bsrc = BT + (size_t)(col0 + br) * K + k0 + bc;
    uint32_t bdst = (uint32_t)__cvta_generic_to_shared(bs + br * BS_STRIDE + bc);
    CP16(bdst, bsrc);
  }
}

template <int MODE>
__device__ __forceinline__ void gemm_body(
    const __half* __restrict__ A, const __half* __restrict__ BT,
    void* __restrict__ Cv, int N, int K, int row0, int col0, __half* smp,
    int vb_base) {
  __half* As = smp;                 // 3 x [128][40]
  __half* Bs = smp + 3 * AS_SZ;     // 3 x [128][40]

  const int tid = threadIdx.x;
  const int lane = tid & 31;
  const int w = tid >> 5;
  const int g = lane >> 2;
  const int t4 = lane & 3;
  const int warp_m = w & 1, warp_n = w >> 1;
  const int m0w = warp_m * 64, n0w = warp_n * 64;

  const int a_lrow = (lane & 7) + ((lane >> 3) & 1) * 8;
  const int a_koff = (lane >> 4) * 8;
  const int b_lrow = (lane & 7) + (lane >> 4) * 8;
  const int b_koff = ((lane >> 3) & 1) * 8;

  float acc[4][8][4];
#pragma unroll
  for (int mi = 0; mi < 4; mi++)
#pragma unroll
    for (int ni = 0; ni < 8; ni++)
#pragma unroll
      for (int e = 0; e < 4; e++) acc[mi][ni][e] = 0.f;

  gemm_issue_slab(tid, A, BT, K, row0, col0, 0, As, Bs);
  CP_COMMIT();
  gemm_issue_slab(tid, A, BT, K, row0, col0, 32, As + AS_SZ, Bs + BS_SZ);
  CP_COMMIT();

  const uint32_t asu0 = (uint32_t)__cvta_generic_to_shared(As);
  const uint32_t bsu0 = (uint32_t)__cvta_generic_to_shared(Bs);

  const int nslab = K >> 5;
  for (int it = 0; it < nslab; it++) {
    CP_WAIT1();
    __syncthreads();
    int kn = it + 2;
    if (kn < nslab)
      gemm_issue_slab(tid, A, BT, K, row0, col0, kn << 5,
                      As + (kn % 3) * AS_SZ, Bs + (kn % 3) * BS_SZ);
    CP_COMMIT();

    const uint32_t asu = asu0 + (it % 3) * AS_SZ * 2;
    const uint32_t bsu = bsu0 + (it % 3) * BS_SZ * 2;
#pragma unroll
    for (int ks = 0; ks < 2; ks++) {
      const int kk = ks * 16;
      uint32_t a[4][4];
#pragma unroll
      for (int mi = 0; mi < 4; mi++) {
        uint32_t ad = asu +
            ((m0w + mi * 16 + a_lrow) * AS_STRIDE + kk + a_koff) * 2;
        LDSM4(a[mi][0], a[mi][1], a[mi][2], a[mi][3], ad);
      }
      uint32_t b[8][2];
#pragma unroll
      for (int nip = 0; nip < 4; nip++) {
        uint32_t bd = bsu +
            ((n0w + nip * 16 + b_lrow) * BS_STRIDE + kk + b_koff) * 2;
        LDSM4(b[2 * nip][0], b[2 * nip][1], b[2 * nip + 1][0],
              b[2 * nip + 1][1], bd);
      }
#pragma unroll
      for (int mi = 0; mi < 4; mi++)
#pragma unroll
        for (int ni = 0; ni < 8; ni++) MMA_F16(acc[mi][ni], a[mi], b[ni]);
    }
  }

#pragma unroll
  for (int mi = 0; mi < 4; mi++) {
    int r0 = row0 + m0w + mi * 16 + g;
#pragma unroll
    for (int ni = 0; ni < 8; ni++) {
      int col = col0 + n0w + ni * 8 + 2 * t4;
      if (MODE == 0) {
        __half* C = (__half*)Cv;
        *(__half2*)(C + (size_t)r0 * N + col) =
            __floats2half2_rn(acc[mi][ni][0], acc[mi][ni][1]);
        *(__half2*)(C + (size_t)(r0 + 8) * N + col) =
            __floats2half2_rn(acc[mi][ni][2], acc[mi][ni][3]);
      } else if (MODE == 1) {
        __half* C = (__half*)Cv;
        int s0 = r0 & (S - 1);
        int b0 = r0 >> 11;
        int d = col & (HD - 1);
        __half* base = C + ((size_t)(b0 * HKV) + vb_base) * HD * S;
        base[(size_t)d * S + s0] = __float2half_rn(acc[mi][ni][0]);
        base[(size_t)(d + 1) * S + s0] = __float2half_rn(acc[mi][ni][1]);
        base[(size_t)d * S + s0 + 8] = __float2half_rn(acc[mi][ni][2]);
        base[(size_t)(d + 1) * S + s0 + 8] = __float2half_rn(acc[mi][ni][3]);
      } else if (MODE == 2) {
        float* C = (float*)Cv;
        *(float2*)(C + (size_t)r0 * N + col) =
            make_float2(acc[mi][ni][0], acc[mi][ni][1]);
        *(float2*)(C + (size_t)(r0 + 8) * N + col) =
            make_float2(acc[mi][ni][2], acc[mi][ni][3]);
      } else {  // MODE 3: fused RoPE. Thread holds cols (2j, 2j+1) of one head.
        __half* C = (__half*)Cv;
        const int s0 = r0 & (S - 1);
        const int jj = (col & 127) >> 1;
        const int cb = col - (col & 127);
        const float theta = exp2f(-(float)jj * 0.20762050593045983f);
        float sn0, cs0, sn1, cs1;
        sincosf((float)s0 * theta, &sn0, &cs0);
        sincosf((float)(s0 + 8) * theta, &sn1, &cs1);
        __half* p0 = C + (size_t)r0 * N + cb + jj;
        __half* p1 = C + (size_t)(r0 + 8) * N + cb + jj;
        p0[0]  = __float2half_rn(acc[mi][ni][0] * cs0 - acc[mi][ni][1] * sn0);
        p0[64] = __float2half_rn(acc[mi][ni][0] * sn0 + acc[mi][ni][1] * cs0);
        p1[0]  = __float2half_rn(acc[mi][ni][2] * cs1 - acc[mi][ni][3] * sn1);
        p1[64] = __float2half_rn(acc[mi][ni][2] * sn1 + acc[mi][ni][3] * cs1);
      }
    }
  }
}

__global__ void __launch_bounds__(128, 2)
qkv_gemm(const __half* __restrict__ xh, const __half* __restrict__ wqT,
         const __half* __restrict__ wkT, const __half* __restrict__ wvT,
         __half* __restrict__ q, __half* __restrict__ k,
         __half* __restrict__ vT) {
  extern __shared__ __half smp[];
  const int bx = blockIdx.x;
  const int row0 = blockIdx.y * 128;
  if (bx < 16) {
    gemm_body<3>(xh, wqT, q, QN, D, row0, bx * 128, smp, 0);        // Q + RoPE
  } else if (bx < 20) {
    gemm_body<3>(xh, wkT, k, KN, D, row0, (bx - 16) * 128, smp, 0); // K + RoPE
  } else {
    int col0 = (bx - 20) * 128;
    gemm_body<1>(xh, wvT, vT, KN, D, row0, col0, smp, col0 >> 7);
  }
}

__global__ void __launch_bounds__(128, 2)
o_gemm(const __half* __restrict__ attnh, const __half* __restrict__ woT,
       float* __restrict__ out) {
  extern __shared__ __half smp[];
  gemm_body<2>(attnh, woT, out, D, QN, blockIdx.y * 128, blockIdx.x * 128, smp, 0);
}

// ---------------------------------------------------------------------------
// Flash attention: 128 threads (4 warps x 16 q-rows = 64 rows), k-tile 128,
// single-buffered K/V with phase-overlapped prefetch, register softmax.
// Fragment loads chunked (4 LDSM groups at a time) to cut register pressure.
// ---------------------------------------------------------------------------
#define QS_STRIDE 136
#define KS_STRIDE 136
#define VT_STRIDE 136
#define ATTN_SMEM_BYTES ((64 * QS_STRIDE + 128 * KS_STRIDE + 128 * VT_STRIDE) * 2)

__device__ __forceinline__ void attn_issue_k(int tid, const __half* src,
                                             __half* dst) {
#pragma unroll
  for (int i = 0; i < 16; i++) {
    int idx = tid + i * 128;
    int n = idx >> 4, c8 = (idx & 15) << 3;
    uint32_t d = (uint32_t)__cvta_generic_to_shared(dst + n * KS_STRIDE + c8);
    CP16(d, src + (size_t)n * KN + c8);
  }
}
__device__ __forceinline__ void attn_issue_v(int tid, const __half* src,
                                             __half* dst) {
#pragma unroll
  for (int i = 0; i < 16; i++) {
    int idx = tid + i * 128;
    int dd = idx >> 4, c8 = (idx & 15) << 3;
    uint32_t d = (uint32_t)__cvta_generic_to_shared(dst + dd * VT_STRIDE + c8);
    CP16(d, src + (size_t)dd * S + c8);
  }
}

__global__ void __launch_bounds__(128, 2)
attn_kernel(const __half* __restrict__ Q, const __half* __restrict__ K,
            const __half* __restrict__ VT, __half* __restrict__ O) {
  extern __shared__ __half smh[];
  __half* Qs = smh;                      // [64][136]
  __half* Ks = Qs + 64 * QS_STRIDE;      // [128][136]
  __half* Vs = Ks + 128 * KS_STRIDE;     // [128][136] (V^T)

  const int tid = threadIdx.x;
  const int lane = tid & 31;
  const int w = tid >> 5;                // 0..3
  const int g = lane >> 2;
  const int t4 = lane & 3;
  const int m0 = w * 16;

  const int a_lrow = (lane & 7) + ((lane >> 3) & 1) * 8;
  const int a_koff = (lane >> 4) * 8;
  const int b_lrow = (lane & 7) + (lane >> 4) * 8;
  const int b_koff = ((lane >> 3) & 1) * 8;

  const uint32_t qsu = (uint32_t)__cvta_generic_to_shared(Qs);
  const uint32_t ksu = (uint32_t)__cvta_generic_to_shared(Ks);
  const uint32_t vsu = (uint32_t)__cvta_generic_to_shared(Vs);

  const int qi = (int)gridDim.x - 1 - (int)blockIdx.x;  // heavy tiles first
  const int bh = blockIdx.y;
  const int b = bh >> 4;
  const int h = bh & 15;
  const int hk = h >> 2;
  const int q0 = qi * 64;

  const __half* qb = Q + (size_t)b * S * QN + h * HD;
  const __half* kb = K + (size_t)b * S * KN + hk * HD;
  const __half* vtb = VT + ((size_t)(b * HKV + hk)) * HD * S;

  const int T = (q0 >> 7) + 1;

  // Prologue: G1 = Q + K0, G2 = V0
#pragma unroll
  for (int i = 0; i < 8; i++) {
    int idx = tid + i * 128;
    int r = idx >> 4, c8 = (idx & 15) << 3;
    uint32_t d = (uint32_t)__cvta_generic_to_shared(Qs + r * QS_STRIDE + c8);
    CP16(d, qb + (size_t)(q0 + r) * QN + c8);
  }
  attn_issue_k(tid, kb, Ks);
  CP_COMMIT();
  attn_issue_v(tid, vtb, Vs);
  CP_COMMIT();

  float oacc[16][4];
#pragma unroll
  for (int ni = 0; ni < 16; ni++)
#pragma unroll
    for (int e = 0; e < 4; e++) oacc[ni][e] = 0.f;

  float m0r = -INFINITY, m1r = -INFINITY;
  float l0r = 0.f, l1r = 0.f;

  const float qk_scale = 0.08838834764831845f;

  for (int t = 0; t < T; t++) {
    const int k0 = t << 7;

    CP_WAIT1();         // K_t (and Q on t=0) ready; V_t may be in flight
    __syncthreads();

    // ---- scores: 16 rows x 128 cols, k = 128, fragments chunked by 4 ----
    float sacc[16][4];
#pragma unroll
    for (int ni = 0; ni < 16; ni++)
#pragma unroll
      for (int e = 0; e < 4; e++) sacc[ni][e] = 0.f;

#pragma unroll
    for (int ks = 0; ks < 8; ks++) {
      const int kk = ks * 16;
      uint32_t a[4];
      uint32_t ad = qsu + ((m0 + a_lrow) * QS_STRIDE + kk + a_koff) * 2;
      LDSM4(a[0], a[1], a[2], a[3], ad);
#pragma unroll
      for (int half = 0; half < 2; half++) {
        uint32_t bfr[8][2];
#pragma unroll
        for (int nip = 0; nip < 4; nip++) {
          int nq = half * 4 + nip;
          uint32_t bd =
              ksu + ((nq * 16 + b_lrow) * KS_STRIDE + kk + b_koff) * 2;
          LDSM4(bfr[2 * nip][0], bfr[2 * nip][1], bfr[2 * nip + 1][0],
                bfr[2 * nip + 1][1], bd);
        }
#pragma unroll
        for (int ni = 0; ni < 8; ni++)
          MMA_F16(sacc[half * 8 + ni], a, bfr[ni]);
      }
    }
    __syncthreads();    // all warps done reading Ks

    // Prefetch K_{t+1} (overlaps softmax below + PV)
    if (t + 1 < T) attn_issue_k(tid, kb + (size_t)(k0 + 128) * KN, Ks);
    CP_COMMIT();

    // ---- scale + causal mask (registers) ----
    const bool diag = (k0 + 127 > q0);
    const int qr0 = q0 + m0 + g, qr1 = qr0 + 8;
#pragma unroll
    for (int ni = 0; ni < 16; ni++) {
      float v0 = sacc[ni][0] * qk_scale;
      float v1 = sacc[ni][1] * qk_scale;
      float v2 = sacc[ni][2] * qk_scale;
      float v3 = sacc[ni][3] * qk_scale;
      if (diag) {
        int kc = k0 + ni * 8 + 2 * t4;
        if (kc > qr0) v0 = -1e30f;
        if (kc + 1 > qr0) v1 = -1e30f;
        if (kc > qr1) v2 = -1e30f;
        if (kc + 1 > qr1) v3 = -1e30f;
      }
      sacc[ni][0] = v0; sacc[ni][1] = v1; sacc[ni][2] = v2; sacc[ni][3] = v3;
    }

    // ---- register softmax (rows g, g+8; reduce across quad t4) ----
    float mx0 = -INFINITY, mx1 = -INFINITY;
#pragma unroll
    for (int ni = 0; ni < 16; ni++) {
      mx0 = fmaxf(mx0, fmaxf(sacc[ni][0], sacc[ni][1]));
      mx1 = fmaxf(mx1, fmaxf(sacc[ni][2], sacc[ni][3]));
    }
    mx0 = fmaxf(mx0, __shfl_xor_sync(0xffffffffu, mx0, 1));
    mx0 = fmaxf(mx0, __shfl_xor_sync(0xffffffffu, mx0, 2));
    mx1 = fmaxf(mx1, __shfl_xor_sync(0xffffffffu, mx1, 1));
    mx1 = fmaxf(mx1, __shfl_xor_sync(0xffffffffu, mx1, 2));
    const float mn0 = fmaxf(m0r, mx0);
    const float mn1 = fmaxf(m1r, mx1);

    // Convert P in place: pack half2 pairs into the sacc registers' slots.
    uint32_t ph0[16], ph1[16];
    float s0 = 0.f, s1 = 0.f;
#pragma unroll
    for (int ni = 0; ni < 16; ni++) {
      __half2 e01 = __floats2half2_rn(__expf(sacc[ni][0] - mn0),
                                      __expf(sacc[ni][1] - mn0));
      __half2 e23 = __floats2half2_rn(__expf(sacc[ni][2] - mn1),
                                      __expf(sacc[ni][3] - mn1));
      ph0[ni] = *(uint32_t*)&e01;
      ph1[ni] = *(uint32_t*)&e23;
      float2 f01 = __half22float2(e01);
      float2 f23 = __half22float2(e23);
      s0 += f01.x + f01.y;
      s1 += f23.x + f23.y;
    }
    s0 += __shfl_xor_sync(0xffffffffu, s0, 1);
    s0 += __shfl_xor_sync(0xffffffffu, s0, 2);
    s1 += __shfl_xor_sync(0xffffffffu, s1, 1);
    s1 += __shfl_xor_sync(0xffffffffu, s1, 2);
    const float al0 = __expf(m0r - mn0);
    const float al1 = __expf(m1r - mn1);
    m0r = mn0; m1r = mn1;
    l0r = l0r * al0 + s0;
    l1r = l1r * al1 + s1;
#pragma unroll
    for (int ni = 0; ni < 16; ni++) {
      oacc[ni][0] *= al0;
      oacc[ni][1] *= al0;
      oacc[ni][2] *= al1;
      oacc[ni][3] *= al1;
    }

    CP_WAIT1();         // V_t ready (K_{t+1} may remain in flight)
    __syncthreads();

    // ---- PV: A from registers (ph), B = V^T, k = 128, chunked by 4 ----
#pragma unroll
    for (int ks = 0; ks < 8; ks++) {
      const int kk = ks * 16;
      uint32_t a[4];
      a[0] = ph0[2 * ks];
      a[1] = ph1[2 * ks];
      a[2] = ph0[2 * ks + 1];
      a[3] = ph1[2 * ks + 1];
#pragma unroll
      for (int half = 0; half < 2; half++) {
        uint32_t bfr[8][2];
#pragma unroll
        for (int nip = 0; nip < 4; nip++) {
          int nq = half * 4 + nip;
          uint32_t bd =
              vsu + ((nq * 16 + b_lrow) * VT_STRIDE + kk + b_koff) * 2;
          LDSM4(bfr[2 * nip][0], bfr[2 * nip][1], bfr[2 * nip + 1][0],
                bfr[2 * nip + 1][1], bd);
        }
#pragma unroll
        for (int ni = 0; ni < 8; ni++)
          MMA_F16(oacc[half * 8 + ni], a, bfr[ni]);
      }
    }
    __syncthreads();    // all warps done reading Vs

    // Prefetch V_{t+1} (overlaps next scores)
    if (t + 1 < T) attn_issue_v(tid, vtb + k0 + 128, Vs);
    CP_COMMIT();
  }

  // ---- finalize: O = half(oacc / l) ----
  {
    const float inv0 = 1.f / l0r;
    const float inv1 = 1.f / l1r;
    __half* o0 = O + (size_t)(b * S + q0 + m0 + g) * QN + h * HD + 2 * t4;
    __half* o1 = o0 + (size_t)8 * QN;
#pragma unroll
    for (int ni = 0; ni < 16; ni++) {
      *(__half2*)(o0 + ni * 8) =
          __floats2half2_rn(oacc[ni][0] * inv0, oacc[ni][1] * inv0);
      *(__half2*)(o1 + ni * 8) =
          __floats2half2_rn(oacc[ni][2] * inv1, oacc[ni][3] * inv1);
    }
  }
}

// ---------------------------------------------------------------------------
extern "C" void kernel_launch(void* const* d_in, const int* in_sizes, int n_in,
                              void* d_out, int out_size) {
  const float* x  = (const float*)d_in[0];
  const float* Wq = (const float*)d_in[1];
  const float* Wk = (const float*)d_in[2];
  const float* Wv = (const float*)d_in[3];
  const float* Wo = (const float*)d_in[4];
  float* out = (float*)d_out;

  __half *xh, *wqT, *wkT, *wvT, *woT, *qh, *kh, *vT, *attnh;
  cudaGetSymbolAddress((void**)&xh, g_xh);
  cudaGetSymbolAddress((void**)&wqT, g_wqT);
  cudaGetSymbolAddress((void**)&wkT, g_wkT);
  cudaGetSymbolAddress((void**)&wvT, g_wvT);
  cudaGetSymbolAddress((void**)&woT, g_woT);
  cudaGetSymbolAddress((void**)&qh, g_qh);
  cudaGetSymbolAddress((void**)&kh, g_kh);
  cudaGetSymbolAddress((void**)&vT, g_vT);
  cudaGetSymbolAddress((void**)&attnh, g_attnh);

  cudaFuncSetAttribute(qkv_gemm, cudaFuncAttributeMaxDynamicSharedMemorySize,
                       GEMM_SMEM_BYTES);
  cudaFuncSetAttribute(o_gemm, cudaFuncAttributeMaxDynamicSharedMemorySize,
                       GEMM_SMEM_BYTES);
  cudaFuncSetAttribute(attn_kernel, cudaFuncAttributeMaxDynamicSharedMemorySize,
                       ATTN_SMEM_BYTES);

  conv_half<<<(M_ROWS * D / 4 + 255) / 256, 256>>>(x, xh, M_ROWS * D / 4);
  transpose_all<<<dim3(64, 64, 4), dim3(32, 8)>>>(Wq, Wk, Wv, Wo,
                                                  wqT, wkT, wvT, woT);

  qkv_gemm<<<dim3(24, M_ROWS / 128), 128, GEMM_SMEM_BYTES>>>(xh, wqT, wkT, wvT,
                                                             qh, kh, vT);
  attn_kernel<<<dim3(S / 64, B * H), 128, ATTN_SMEM_BYTES>>>(qh, kh, vT, attnh);
  o_gemm<<<dim3(D / 128, M_ROWS / 128), 128, GEMM_SMEM_BYTES>>>(attnh, woT, out);
}

// round 17
// speedup vs baseline: 1.0543x; 1.0079x over previous
#include <cuda_runtime.h>
#include <cuda_fp16.h>
#include <math.h>
#include <stdint.h>

#define B 2
#define S 2048
#define D 2048
#define H 16
#define HKV 4
#define HD 128
#define M_ROWS (B*S)     // 4096
#define QN (H*HD)        // 2048
#define KN (HKV*HD)      // 512

// Scratch (allocation-free: device globals), fp16 operands everywhere
__device__ __half g_xh[(size_t)M_ROWS * D];
__device__ __half g_wqT[(size_t)QN * D];    // [N][K]
__device__ __half g_wkT[(size_t)KN * D];
__device__ __half g_wvT[(size_t)KN * D];
__device__ __half g_woT[(size_t)D * QN];
__device__ __half g_qh[(size_t)M_ROWS * QN];
__device__ __half g_kh[(size_t)M_ROWS * KN];
__device__ __half g_vT[(size_t)B * HKV * HD * S];  // [b][hk][d][s]
__device__ __half g_attnh[(size_t)M_ROWS * QN];

#define MMA_F16(c, a, b)                                                      \
  asm("mma.sync.aligned.m16n8k16.row.col.f32.f16.f16.f32 "                    \
      "{%0,%1,%2,%3},{%4,%5,%6,%7},{%8,%9},{%0,%1,%2,%3};"                    \
      : "+f"(c[0]), "+f"(c[1]), "+f"(c[2]), "+f"(c[3])                        \
      : "r"(a[0]), "r"(a[1]), "r"(a[2]), "r"(a[3]), "r"(b[0]), "r"(b[1]))

#define LDSM4(r0, r1, r2, r3, addr)                                           \
  asm volatile("ldmatrix.sync.aligned.m8n8.x4.shared.b16 {%0,%1,%2,%3}, [%4];"\
               : "=r"(r0), "=r"(r1), "=r"(r2), "=r"(r3) : "r"(addr))

#define CP16(dst, src)                                                        \
  asm volatile("cp.async.cg.shared.global [%0], [%1], 16;" ::"r"(dst), "l"(src))
#define CP_COMMIT() asm volatile("cp.async.commit_group;")
#define CP_WAIT1()  asm volatile("cp.async.wait_group 1;")

// ---------------------------------------------------------------------------
// Fused prep: jobs 0..3 = weight transpose+convert (32x32 tiles);
// jobs z>=4 rows of x convert handled by x-grid portion (y dim).
// Grid: (64, 68, 4) is wasteful; instead use z in [0,4]:
//   z<4 : transpose job z, tiles (x, y) over (C/32, R/32)
//   z==4: x convert, linear tiles (x + 64*y) * 1024 float4s
// ---------------------------------------------------------------------------
__global__ void prep_all(const float* __restrict__ x,
                         const float* __restrict__ Wq,
                         const float* __restrict__ Wk,
                         const float* __restrict__ Wv,
                         const float* __restrict__ Wo,
                         __half* __restrict__ xh,
                         __half* __restrict__ wqT, __half* __restrict__ wkT,
                         __half* __restrict__ wvT, __half* __restrict__ woT) {
  if (blockIdx.z == 4) {
    // x convert: 4096*2048 floats = 2M float4 = 8192 blocks of 256 over grid x,y
    int blk = blockIdx.y * 64 + blockIdx.x;   // 0..4351 used of 64x68
    int i = blk * 256 + threadIdx.y * 32 + threadIdx.x;
    const int n4 = M_ROWS * D / 4;            // 2,097,152
    // grid provides 64*68=4352 blocks * 256 thr = 1,114,112 lanes; stride loop
    for (; i < n4; i += 4352 * 256) {
      float4 v = *(const float4*)(x + 4 * (size_t)i);
      *(__half2*)(xh + 4 * (size_t)i) = __floats2half2_rn(v.x, v.y);
      *(__half2*)(xh + 4 * (size_t)i + 2) = __floats2half2_rn(v.z, v.w);
    }
    return;
  }
  __shared__ float t[32][33];
  const float* src;
  __half* dst;
  int R, C;
  switch (blockIdx.z) {
    case 0: src = Wq; dst = wqT; R = D;  C = QN; break;
    case 1: src = Wk; dst = wkT; R = D;  C = KN; break;
    case 2: src = Wv; dst = wvT; R = D;  C = KN; break;
    default: src = Wo; dst = woT; R = QN; C = D;  break;
  }
  int c0 = blockIdx.x * 32, r0 = blockIdx.y * 32;
  if (c0 >= C || r0 >= R) return;
  int xx = threadIdx.x, yy = threadIdx.y;  // 32 x 8
#pragma unroll
  for (int i = 0; i < 32; i += 8)
    t[yy + i][xx] = src[(size_t)(r0 + yy + i) * C + c0 + xx];
  __syncthreads();
#pragma unroll
  for (int i = 0; i < 32; i += 8)
    dst[(size_t)(c0 + yy + i) * R + r0 + xx] = __float2half_rn(t[xx][yy + i]);
}

// ---------------------------------------------------------------------------
// fp16 MMA GEMM: 128x128x32 block tile, 128 threads (4 warps, warp 64x64),
// 3-buffer single-barrier cp.async pipeline, ldmatrix fragments, 2 CTAs/SM.
// Epilogues: 0 half, 1 V^T half, 2 fp32, 3 half + fused RoPE (Q/K proj).
// ---------------------------------------------------------------------------
#define AS_STRIDE 40
#define BS_STRIDE 40
#define AS_SZ (128 * AS_STRIDE)
#define BS_SZ (128 * BS_STRIDE)
#define GEMM_SMEM_BYTES (3 * (AS_SZ + BS_SZ) * 2)

__device__ __forceinline__ void gemm_issue_slab(
    int tid, const __half* __restrict__ A, const __half* __restrict__ BT,
    int K, int row0, int col0, int k0, __half* as, __half* bs) {
#pragma unroll
  for (int l = 0; l < 4; l++) {
    int idx = tid + l * 128;
    int ar = idx >> 2, ac = (idx & 3) << 3;
    const __half* asrc = A + (size_t)(row0 + ar) * K + k0 + ac;
    uint32_t adst = (uint32_t)__cvta_generic_to_shared(as + ar * AS_STRIDE + ac);
    CP16(adst, asrc);
  }
#pragma unroll
  for (int l = 0; l < 4; l++) {
    int idx = tid + l * 128;
    int br = idx >> 2, bc = (idx & 3) << 3;
    const __half* bsrc = BT + (size_t)(col0 + br) * K + k0 + bc;
    uint32_t bdst = (uint32_t)__cvta_generic_to_shared(bs + br * BS_STRIDE + bc);
    CP16(bdst, bsrc);
  }
}

template <int MODE>
__device__ __forceinline__ void gemm_body(
    const __half* __restrict__ A, const __half* __restrict__ BT,
    void* __restrict__ Cv, int N, int K, int row0, int col0, __half* smp,
    int vb_base) {
  __half* As = smp;                 // 3 x [128][40]
  __half* Bs = smp + 3 * AS_SZ;     // 3 x [128][40]

  const int tid = threadIdx.x;
  const int lane = tid & 31;
  const int w = tid >> 5;
  const int g = lane >> 2;
  const int t4 = lane & 3;
  const int warp_m = w & 1, warp_n = w >> 1;
  const int m0w = warp_m * 64, n0w = warp_n * 64;

  const int a_lrow = (lane & 7) + ((lane >> 3) & 1) * 8;
  const int a_koff = (lane >> 4) * 8;
  const int b_lrow = (lane & 7) + (lane >> 4) * 8;
  const int b_koff = ((lane >> 3) & 1) * 8;

  float acc[4][8][4];
#pragma unroll
  for (int mi = 0; mi < 4; mi++)
#pragma unroll
    for (int ni = 0; ni < 8; ni++)
#pragma unroll
      for (int e = 0; e < 4; e++) acc[mi][ni][e] = 0.f;

  gemm_issue_slab(tid, A, BT, K, row0, col0, 0, As, Bs);
  CP_COMMIT();
  gemm_issue_slab(tid, A, BT, K, row0, col0, 32, As + AS_SZ, Bs + BS_SZ);
  CP_COMMIT();

  const uint32_t asu0 = (uint32_t)__cvta_generic_to_shared(As);
  const uint32_t bsu0 = (uint32_t)__cvta_generic_to_shared(Bs);

  const int nslab = K >> 5;
  for (int it = 0; it < nslab; it++) {
    CP_WAIT1();
    __syncthreads();
    int kn = it + 2;
    if (kn < nslab)
      gemm_issue_slab(tid, A, BT, K, row0, col0, kn << 5,
                      As + (kn % 3) * AS_SZ, Bs + (kn % 3) * BS_SZ);
    CP_COMMIT();

    const uint32_t asu = asu0 + (it % 3) * AS_SZ * 2;
    const uint32_t bsu = bsu0 + (it % 3) * BS_SZ * 2;
#pragma unroll
    for (int ks = 0; ks < 2; ks++) {
      const int kk = ks * 16;
      uint32_t a[4][4];
#pragma unroll
      for (int mi = 0; mi < 4; mi++) {
        uint32_t ad = asu +
            ((m0w + mi * 16 + a_lrow) * AS_STRIDE + kk + a_koff) * 2;
        LDSM4(a[mi][0], a[mi][1], a[mi][2], a[mi][3], ad);
      }
      uint32_t b[8][2];
#pragma unroll
      for (int nip = 0; nip < 4; nip++) {
        uint32_t bd = bsu +
            ((n0w + nip * 16 + b_lrow) * BS_STRIDE + kk + b_koff) * 2;
        LDSM4(b[2 * nip][0], b[2 * nip][1], b[2 * nip + 1][0],
              b[2 * nip + 1][1], bd);
      }
#pragma unroll
      for (int mi = 0; mi < 4; mi++)
#pragma unroll
        for (int ni = 0; ni < 8; ni++) MMA_F16(acc[mi][ni], a[mi], b[ni]);
    }
  }

#pragma unroll
  for (int mi = 0; mi < 4; mi++) {
    int r0 = row0 + m0w + mi * 16 + g;
#pragma unroll
    for (int ni = 0; ni < 8; ni++) {
      int col = col0 + n0w + ni * 8 + 2 * t4;
      if (MODE == 0) {
        __half* C = (__half*)Cv;
        *(__half2*)(C + (size_t)r0 * N + col) =
            __floats2half2_rn(acc[mi][ni][0], acc[mi][ni][1]);
        *(__half2*)(C + (size_t)(r0 + 8) * N + col) =
            __floats2half2_rn(acc[mi][ni][2], acc[mi][ni][3]);
      } else if (MODE == 1) {
        __half* C = (__half*)Cv;
        int s0 = r0 & (S - 1);
        int b0 = r0 >> 11;
        int d = col & (HD - 1);
        __half* base = C + ((size_t)(b0 * HKV) + vb_base) * HD * S;
        base[(size_t)d * S + s0] = __float2half_rn(acc[mi][ni][0]);
        base[(size_t)(d + 1) * S + s0] = __float2half_rn(acc[mi][ni][1]);
        base[(size_t)d * S + s0 + 8] = __float2half_rn(acc[mi][ni][2]);
        base[(size_t)(d + 1) * S + s0 + 8] = __float2half_rn(acc[mi][ni][3]);
      } else if (MODE == 2) {
        float* C = (float*)Cv;
        *(float2*)(C + (size_t)r0 * N + col) =
            make_float2(acc[mi][ni][0], acc[mi][ni][1]);
        *(float2*)(C + (size_t)(r0 + 8) * N + col) =
            make_float2(acc[mi][ni][2], acc[mi][ni][3]);
      } else {  // MODE 3: fused RoPE. Thread holds cols (2j, 2j+1) of one head.
        __half* C = (__half*)Cv;
        const int s0 = r0 & (S - 1);
        const int jj = (col & 127) >> 1;
        const int cb = col - (col & 127);
        const float theta = exp2f(-(float)jj * 0.20762050593045983f);
        float sn0, cs0, sn1, cs1;
        sincosf((float)s0 * theta, &sn0, &cs0);
        sincosf((float)(s0 + 8) * theta, &sn1, &cs1);
        __half* p0 = C + (size_t)r0 * N + cb + jj;
        __half* p1 = C + (size_t)(r0 + 8) * N + cb + jj;
        p0[0]  = __float2half_rn(acc[mi][ni][0] * cs0 - acc[mi][ni][1] * sn0);
        p0[64] = __float2half_rn(acc[mi][ni][0] * sn0 + acc[mi][ni][1] * cs0);
        p1[0]  = __float2half_rn(acc[mi][ni][2] * cs1 - acc[mi][ni][3] * sn1);
        p1[64] = __float2half_rn(acc[mi][ni][2] * sn1 + acc[mi][ni][3] * cs1);
      }
    }
  }
}

__global__ void __launch_bounds__(128, 2)
qkv_gemm(const __half* __restrict__ xh, const __half* __restrict__ wqT,
         const __half* __restrict__ wkT, const __half* __restrict__ wvT,
         __half* __restrict__ q, __half* __restrict__ k,
         __half* __restrict__ vT) {
  extern __shared__ __half smp[];
  const int bx = blockIdx.x;
  const int row0 = blockIdx.y * 128;
  if (bx < 16) {
    gemm_body<3>(xh, wqT, q, QN, D, row0, bx * 128, smp, 0);        // Q + RoPE
  } else if (bx < 20) {
    gemm_body<3>(xh, wkT, k, KN, D, row0, (bx - 16) * 128, smp, 0); // K + RoPE
  } else {
    int col0 = (bx - 20) * 128;
    gemm_body<1>(xh, wvT, vT, KN, D, row0, col0, smp, col0 >> 7);
  }
}

__global__ void __launch_bounds__(128, 2)
o_gemm(const __half* __restrict__ attnh, const __half* __restrict__ woT,
       float* __restrict__ out) {
  extern __shared__ __half smp[];
  gemm_body<2>(attnh, woT, out, D, QN, blockIdx.y * 128, blockIdx.x * 128, smp, 0);
}

// ---------------------------------------------------------------------------
// Flash attention (R16, best measured): 128 threads (4 warps x 16 q-rows),
// k-tile 128, single-buffered K/V phase-overlapped prefetch, chunked frags.
// ---------------------------------------------------------------------------
#define QS_STRIDE 136
#define KS_STRIDE 136
#define VT_STRIDE 136
#define ATTN_SMEM_BYTES ((64 * QS_STRIDE + 128 * KS_STRIDE + 128 * VT_STRIDE) * 2)

__device__ __forceinline__ void attn_issue_k(int tid, const __half* src,
                                             __half* dst) {
#pragma unroll
  for (int i = 0; i < 16; i++) {
    int idx = tid + i * 128;
    int n = idx >> 4, c8 = (idx & 15) << 3;
    uint32_t d = (uint32_t)__cvta_generic_to_shared(dst + n * KS_STRIDE + c8);
    CP16(d, src + (size_t)n * KN + c8);
  }
}
__device__ __forceinline__ void attn_issue_v(int tid, const __half* src,
                                             __half* dst) {
#pragma unroll
  for (int i = 0; i < 16; i++) {
    int idx = tid + i * 128;
    int dd = idx >> 4, c8 = (idx & 15) << 3;
    uint32_t d = (uint32_t)__cvta_generic_to_shared(dst + dd * VT_STRIDE + c8);
    CP16(d, src + (size_t)dd * S + c8);
  }
}

__global__ void __launch_bounds__(128, 2)
attn_kernel(const __half* __restrict__ Q, const __half* __restrict__ K,
            const __half* __restrict__ VT, __half* __restrict__ O) {
  extern __shared__ __half smh[];
  __half* Qs = smh;                      // [64][136]
  __half* Ks = Qs + 64 * QS_STRIDE;      // [128][136]
  __half* Vs = Ks + 128 * KS_STRIDE;     // [128][136] (V^T)

  const int tid = threadIdx.x;
  const int lane = tid & 31;
  const int w = tid >> 5;                // 0..3
  const int g = lane >> 2;
  const int t4 = lane & 3;
  const int m0 = w * 16;

  const int a_lrow = (lane & 7) + ((lane >> 3) & 1) * 8;
  const int a_koff = (lane >> 4) * 8;
  const int b_lrow = (lane & 7) + (lane >> 4) * 8;
  const int b_koff = ((lane >> 3) & 1) * 8;

  const uint32_t qsu = (uint32_t)__cvta_generic_to_shared(Qs);
  const uint32_t ksu = (uint32_t)__cvta_generic_to_shared(Ks);
  const uint32_t vsu = (uint32_t)__cvta_generic_to_shared(Vs);

  const int qi = (int)gridDim.x - 1 - (int)blockIdx.x;  // heavy tiles first
  const int bh = blockIdx.y;
  const int b = bh >> 4;
  const int h = bh & 15;
  const int hk = h >> 2;
  const int q0 = qi * 64;

  const __half* qb = Q + (size_t)b * S * QN + h * HD;
  const __half* kb = K + (size_t)b * S * KN + hk * HD;
  const __half* vtb = VT + ((size_t)(b * HKV + hk)) * HD * S;

  const int T = (q0 >> 7) + 1;

  // Prologue: G1 = Q + K0, G2 = V0
#pragma unroll
  for (int i = 0; i < 8; i++) {
    int idx = tid + i * 128;
    int r = idx >> 4, c8 = (idx & 15) << 3;
    uint32_t d = (uint32_t)__cvta_generic_to_shared(Qs + r * QS_STRIDE + c8);
    CP16(d, qb + (size_t)(q0 + r) * QN + c8);
  }
  attn_issue_k(tid, kb, Ks);
  CP_COMMIT();
  attn_issue_v(tid, vtb, Vs);
  CP_COMMIT();

  float oacc[16][4];
#pragma unroll
  for (int ni = 0; ni < 16; ni++)
#pragma unroll
    for (int e = 0; e < 4; e++) oacc[ni][e] = 0.f;

  float m0r = -INFINITY, m1r = -INFINITY;
  float l0r = 0.f, l1r = 0.f;

  const float qk_scale = 0.08838834764831845f;

  for (int t = 0; t < T; t++) {
    const int k0 = t << 7;

    CP_WAIT1();         // K_t (and Q on t=0) ready; V_t may be in flight
    __syncthreads();

    // ---- scores: 16 rows x 128 cols, k = 128, fragments chunked by 4 ----
    float sacc[16][4];
#pragma unroll
    for (int ni = 0; ni < 16; ni++)
#pragma unroll
      for (int e = 0; e < 4; e++) sacc[ni][e] = 0.f;

#pragma unroll
    for (int ks = 0; ks < 8; ks++) {
      const int kk = ks * 16;
      uint32_t a[4];
      uint32_t ad = qsu + ((m0 + a_lrow) * QS_STRIDE + kk + a_koff) * 2;
      LDSM4(a[0], a[1], a[2], a[3], ad);
#pragma unroll
      for (int half = 0; half < 2; half++) {
        uint32_t bfr[8][2];
#pragma unroll
        for (int nip = 0; nip < 4; nip++) {
          int nq = half * 4 + nip;
          uint32_t bd =
              ksu + ((nq * 16 + b_lrow) * KS_STRIDE + kk + b_koff) * 2;
          LDSM4(bfr[2 * nip][0], bfr[2 * nip][1], bfr[2 * nip + 1][0],
                bfr[2 * nip + 1][1], bd);
        }
#pragma unroll
        for (int ni = 0; ni < 8; ni++)
          MMA_F16(sacc[half * 8 + ni], a, bfr[ni]);
      }
    }
    __syncthreads();    // all warps done reading Ks

    // Prefetch K_{t+1} (overlaps softmax below + PV)
    if (t + 1 < T) attn_issue_k(tid, kb + (size_t)(k0 + 128) * KN, Ks);
    CP_COMMIT();

    // ---- scale + causal mask (registers) ----
    const bool diag = (k0 + 127 > q0);
    const int qr0 = q0 + m0 + g, qr1 = qr0 + 8;
#pragma unroll
    for (int ni = 0; ni < 16; ni++) {
      float v0 = sacc[ni][0] * qk_scale;
      float v1 = sacc[ni][1] * qk_scale;
      float v2 = sacc[ni][2] * qk_scale;
      float v3 = sacc[ni][3] * qk_scale;
      if (diag) {
        int kc = k0 + ni * 8 + 2 * t4;
        if (kc > qr0) v0 = -1e30f;
        if (kc + 1 > qr0) v1 = -1e30f;
        if (kc > qr1) v2 = -1e30f;
        if (kc + 1 > qr1) v3 = -1e30f;
      }
      sacc[ni][0] = v0; sacc[ni][1] = v1; sacc[ni][2] = v2; sacc[ni][3] = v3;
    }

    // ---- register softmax (rows g, g+8; reduce across quad t4) ----
    float mx0 = -INFINITY, mx1 = -INFINITY;
#pragma unroll
    for (int ni = 0; ni < 16; ni++) {
      mx0 = fmaxf(mx0, fmaxf(sacc[ni][0], sacc[ni][1]));
      mx1 = fmaxf(mx1, fmaxf(sacc[ni][2], sacc[ni][3]));
    }
    mx0 = fmaxf(mx0, __shfl_xor_sync(0xffffffffu, mx0, 1));
    mx0 = fmaxf(mx0, __shfl_xor_sync(0xffffffffu, mx0, 2));
    mx1 = fmaxf(mx1, __shfl_xor_sync(0xffffffffu, mx1, 1));
    mx1 = fmaxf(mx1, __shfl_xor_sync(0xffffffffu, mx1, 2));
    const float mn0 = fmaxf(m0r, mx0);
    const float mn1 = fmaxf(m1r, mx1);

    uint32_t ph0[16], ph1[16];
    float s0 = 0.f, s1 = 0.f;
#pragma unroll
    for (int ni = 0; ni < 16; ni++) {
      __half2 e01 = __floats2half2_rn(__expf(sacc[ni][0] - mn0),
                                      __expf(sacc[ni][1] - mn0));
      __half2 e23 = __floats2half2_rn(__expf(sacc[ni][2] - mn1),
                                      __expf(sacc[ni][3] - mn1));
      ph0[ni] = *(uint32_t*)&e01;
      ph1[ni] = *(uint32_t*)&e23;
      float2 f01 = __half22float2(e01);
      float2 f23 = __half22float2(e23);
      s0 += f01.x + f01.y;
      s1 += f23.x + f23.y;
    }
    s0 += __shfl_xor_sync(0xffffffffu, s0, 1);
    s0 += __shfl_xor_sync(0xffffffffu, s0, 2);
    s1 += __shfl_xor_sync(0xffffffffu, s1, 1);
    s1 += __shfl_xor_sync(0xffffffffu, s1, 2);
    const float al0 = __expf(m0r - mn0);
    const float al1 = __expf(m1r - mn1);
    m0r = mn0; m1r = mn1;
    l0r = l0r * al0 + s0;
    l1r = l1r * al1 + s1;
#pragma unroll
    for (int ni = 0; ni < 16; ni++) {
      oacc[ni][0] *= al0;
      oacc[ni][1] *= al0;
      oacc[ni][2] *= al1;
      oacc[ni][3] *= al1;
    }

    CP_WAIT1();         // V_t ready (K_{t+1} may remain in flight)
    __syncthreads();

    // ---- PV: A from registers (ph), B = V^T, k = 128, chunked by 4 ----
#pragma unroll
    for (int ks = 0; ks < 8; ks++) {
      const int kk = ks * 16;
      uint32_t a[4];
      a[0] = ph0[2 * ks];
      a[1] = ph1[2 * ks];
      a[2] = ph0[2 * ks + 1];
      a[3] = ph1[2 * ks + 1];
#pragma unroll
      for (int half = 0; half < 2; half++) {
        uint32_t bfr[8][2];
#pragma unroll
        for (int nip = 0; nip < 4; nip++) {
          int nq = half * 4 + nip;
          uint32_t bd =
              vsu + ((nq * 16 + b_lrow) * VT_STRIDE + kk + b_koff) * 2;
          LDSM4(bfr[2 * nip][0], bfr[2 * nip][1], bfr[2 * nip + 1][0],
                bfr[2 * nip + 1][1], bd);
        }
#pragma unroll
        for (int ni = 0; ni < 8; ni++)
          MMA_F16(oacc[half * 8 + ni], a, bfr[ni]);
      }
    }
    __syncthreads();    // all warps done reading Vs

    // Prefetch V_{t+1} (overlaps next scores)
    if (t + 1 < T) attn_issue_v(tid, vtb + k0 + 128, Vs);
    CP_COMMIT();
  }

  // ---- finalize: O = half(oacc / l) ----
  {
    const float inv0 = 1.f / l0r;
    const float inv1 = 1.f / l1r;
    __half* o0 = O + (size_t)(b * S + q0 + m0 + g) * QN + h * HD + 2 * t4;
    __half* o1 = o0 + (size_t)8 * QN;
#pragma unroll
    for (int ni = 0; ni < 16; ni++) {
      *(__half2*)(o0 + ni * 8) =
          __floats2half2_rn(oacc[ni][0] * inv0, oacc[ni][1] * inv0);
      *(__half2*)(o1 + ni * 8) =
          __floats2half2_rn(oacc[ni][2] * inv1, oacc[ni][3] * inv1);
    }
  }
}

// ---------------------------------------------------------------------------
extern "C" void kernel_launch(void* const* d_in, const int* in_sizes, int n_in,
                              void* d_out, int out_size) {
  const float* x  = (const float*)d_in[0];
  const float* Wq = (const float*)d_in[1];
  const float* Wk = (const float*)d_in[2];
  const float* Wv = (const float*)d_in[3];
  const float* Wo = (const float*)d_in[4];
  float* out = (float*)d_out;

  __half *xh, *wqT, *wkT, *wvT, *woT, *qh, *kh, *vT, *attnh;
  cudaGetSymbolAddress((void**)&xh, g_xh);
  cudaGetSymbolAddress((void**)&wqT, g_wqT);
  cudaGetSymbolAddress((void**)&wkT, g_wkT);
  cudaGetSymbolAddress((void**)&wvT, g_wvT);
  cudaGetSymbolAddress((void**)&woT, g_woT);
  cudaGetSymbolAddress((void**)&qh, g_qh);
  cudaGetSymbolAddress((void**)&kh, g_kh);
  cudaGetSymbolAddress((void**)&vT, g_vT);
  cudaGetSymbolAddress((void**)&attnh, g_attnh);

  cudaFuncSetAttribute(qkv_gemm, cudaFuncAttributeMaxDynamicSharedMemorySize,
                       GEMM_SMEM_BYTES);
  cudaFuncSetAttribute(o_gemm, cudaFuncAttributeMaxDynamicSharedMemorySize,
                       GEMM_SMEM_BYTES);
  cudaFuncSetAttribute(attn_kernel, cudaFuncAttributeMaxDynamicSharedMemorySize,
                       ATTN_SMEM_BYTES);

  // Fused prep: z=0..3 weight transposes (64x64 tile grid), z=4 x-convert
  prep_all<<<dim3(64, 68, 5), dim3(32, 8)>>>(x, Wq, Wk, Wv, Wo, xh,
                                             wqT, wkT, wvT, woT);

  qkv_gemm<<<dim3(24, M_ROWS / 128), 128, GEMM_SMEM_BYTES>>>(xh, wqT, wkT, wvT,
                                                             qh, kh, vT);
  attn_kernel<<<dim3(S / 64, B * H), 128, ATTN_SMEM_BYTES>>>(qh, kh, vT, attnh);
  o_gemm<<<dim3(D / 128, M_ROWS / 128), 128, GEMM_SMEM_BYTES>>>(attnh, woT, out);
}